// round 1
// baseline (speedup 1.0000x reference)
#include <cuda_runtime.h>

// MSAPairWeightedAverage — fp32 baseline, structured for bandwidth & issue efficiency.
// S=512, I=384, C_MSA=64, C_Z=128, H=8, C=32 (H*C=256)

#define S_DIM 512
#define I_DIM 384
#define CM    64
#define CZ    128
#define H_DIM 8
#define C_DIM 32
#define HC    256
#define LN_EPS 1e-5f

// Scratch (allocation-free rule: __device__ globals)
__device__ float g_v[(size_t)S_DIM * I_DIM * HC];      // [s][j][hc]
__device__ float g_gate[(size_t)S_DIM * I_DIM * HC];   // [s][i][hc], sigmoid applied
__device__ float g_bias[(size_t)I_DIM * H_DIM * I_DIM];// [i][h][j]
__device__ float g_w[(size_t)H_DIM * I_DIM * I_DIM];   // [h][j][i]  (softmax weights, transposed)

// ---------------------------------------------------------------------------
// K1: LN(msa) then v = msa_n @ W_v ; gate = sigmoid(msa_n @ W_gate)
// 256 threads, 16 rows/block. W (64x256) in SMEM, msa_n transposed [k][r].
// ---------------------------------------------------------------------------
__global__ __launch_bounds__(256) void k1_v_gate(
    const float* __restrict__ msa,
    const float* __restrict__ ln_g, const float* __restrict__ ln_b,
    const float* __restrict__ Wv,   const float* __restrict__ Wg)
{
    extern __shared__ float sm[];
    float* Wsh   = sm;               // 64*256 = 16384 floats
    float* msa_t = sm + 64 * 256;    // [64][16] = 1024 floats

    const int t    = threadIdx.x;
    const int lane = t & 31;
    const int warp = t >> 5;
    const int rb   = blockIdx.x * 16;   // row base into [S*I]

    // LayerNorm: each warp handles 2 rows
    #pragma unroll
    for (int rr = 0; rr < 2; rr++) {
        const int r = warp * 2 + rr;
        const float* x = msa + (size_t)(rb + r) * CM;
        float x0 = x[lane], x1 = x[lane + 32];
        float s = x0 + x1, s2 = x0 * x0 + x1 * x1;
        #pragma unroll
        for (int o = 16; o; o >>= 1) {
            s  += __shfl_xor_sync(0xffffffffu, s,  o);
            s2 += __shfl_xor_sync(0xffffffffu, s2, o);
        }
        float mu  = s * (1.f / 64.f);
        float var = s2 * (1.f / 64.f) - mu * mu;
        float rs  = rsqrtf(var + LN_EPS);
        msa_t[lane * 16 + r]        = (x0 - mu) * rs * ln_g[lane]      + ln_b[lane];
        msa_t[(lane + 32) * 16 + r] = (x1 - mu) * rs * ln_g[lane + 32] + ln_b[lane + 32];
    }

    for (int phase = 0; phase < 2; phase++) {
        const float* W = phase ? Wg : Wv;
        __syncthreads();  // LN done / previous phase reads done
        {   // load W into SMEM (4096 float4)
            const float4* src = (const float4*)W;
            float4* dst = (float4*)Wsh;
            #pragma unroll
            for (int u = 0; u < 16; u++) dst[t + 256 * u] = src[t + 256 * u];
        }
        __syncthreads();

        float acc[16];
        #pragma unroll
        for (int r = 0; r < 16; r++) acc[r] = 0.f;

        #pragma unroll 8
        for (int k = 0; k < 64; k++) {
            float wv = Wsh[k * 256 + t];
            const float4* m4 = (const float4*)(msa_t + k * 16);
            float4 m0 = m4[0], m1 = m4[1], m2 = m4[2], m3 = m4[3];
            acc[0]  += m0.x * wv; acc[1]  += m0.y * wv; acc[2]  += m0.z * wv; acc[3]  += m0.w * wv;
            acc[4]  += m1.x * wv; acc[5]  += m1.y * wv; acc[6]  += m1.z * wv; acc[7]  += m1.w * wv;
            acc[8]  += m2.x * wv; acc[9]  += m2.y * wv; acc[10] += m2.z * wv; acc[11] += m2.w * wv;
            acc[12] += m3.x * wv; acc[13] += m3.y * wv; acc[14] += m3.z * wv; acc[15] += m3.w * wv;
        }

        float* outp = phase ? g_gate : g_v;
        #pragma unroll
        for (int r = 0; r < 16; r++) {
            float val = acc[r];
            if (phase) val = 1.f / (1.f + __expf(-val));
            outp[(size_t)(rb + r) * HC + t] = val;
        }
    }
}

// ---------------------------------------------------------------------------
// K2: bias[i][h][j] = LN(pair[i][j]) @ W_bias   (one pair row per block)
// ---------------------------------------------------------------------------
__global__ __launch_bounds__(128) void k2_bias(
    const float* __restrict__ pair,
    const float* __restrict__ gz, const float* __restrict__ bz,
    const float* __restrict__ Wb)
{
    __shared__ float red[8];
    __shared__ float stats[2];
    __shared__ float hacc[4][8];

    const int t = threadIdx.x;   // 128
    const int lane = t & 31, warp = t >> 5;
    const int row = blockIdx.x;               // i*384 + j
    const int i = row / I_DIM, j = row - i * I_DIM;

    float x = pair[(size_t)row * CZ + t];
    float s = x, s2 = x * x;
    #pragma unroll
    for (int o = 16; o; o >>= 1) {
        s  += __shfl_xor_sync(0xffffffffu, s,  o);
        s2 += __shfl_xor_sync(0xffffffffu, s2, o);
    }
    if (lane == 0) { red[warp] = s; red[warp + 4] = s2; }
    __syncthreads();
    if (t == 0) {
        float ts  = red[0] + red[1] + red[2] + red[3];
        float ts2 = red[4] + red[5] + red[6] + red[7];
        float mu  = ts * (1.f / 128.f);
        float var = ts2 * (1.f / 128.f) - mu * mu;
        stats[0] = mu; stats[1] = rsqrtf(var + LN_EPS);
    }
    __syncthreads();
    float xn = (x - stats[0]) * stats[1] * gz[t] + bz[t];

    const float4* wb4 = (const float4*)(Wb + t * 8);
    float4 wa = wb4[0], wbv = wb4[1];
    float p[8];
    p[0] = xn * wa.x;  p[1] = xn * wa.y;  p[2] = xn * wa.z;  p[3] = xn * wa.w;
    p[4] = xn * wbv.x; p[5] = xn * wbv.y; p[6] = xn * wbv.z; p[7] = xn * wbv.w;
    #pragma unroll
    for (int h = 0; h < 8; h++) {
        #pragma unroll
        for (int o = 16; o; o >>= 1) p[h] += __shfl_xor_sync(0xffffffffu, p[h], o);
    }
    if (lane == 0) {
        #pragma unroll
        for (int h = 0; h < 8; h++) hacc[warp][h] = p[h];
    }
    __syncthreads();
    if (t < 8) {
        float sum = hacc[0][t] + hacc[1][t] + hacc[2][t] + hacc[3][t];
        g_bias[((size_t)i * H_DIM + t) * I_DIM + j] = sum;
    }
}

// ---------------------------------------------------------------------------
// K3: w[h][j][i] = softmax_j(bias[i][h][j])   (one (i,h) per block)
// ---------------------------------------------------------------------------
__global__ __launch_bounds__(128) void k3_softmax()
{
    __shared__ float red[4];
    __shared__ float bval;

    const int t = threadIdx.x;  // 128
    const int lane = t & 31, warp = t >> 5;
    const int b = blockIdx.x;   // i*8 + h
    const int i = b >> 3, h = b & 7;

    const float* src = g_bias + ((size_t)i * H_DIM + h) * I_DIM;
    float x0 = src[t], x1 = src[t + 128], x2 = src[t + 256];

    float m = fmaxf(x0, fmaxf(x1, x2));
    #pragma unroll
    for (int o = 16; o; o >>= 1) m = fmaxf(m, __shfl_xor_sync(0xffffffffu, m, o));
    if (lane == 0) red[warp] = m;
    __syncthreads();
    if (t == 0) bval = fmaxf(fmaxf(red[0], red[1]), fmaxf(red[2], red[3]));
    __syncthreads();
    const float mx = bval;

    float e0 = __expf(x0 - mx), e1 = __expf(x1 - mx), e2 = __expf(x2 - mx);
    float s = e0 + e1 + e2;
    #pragma unroll
    for (int o = 16; o; o >>= 1) s += __shfl_xor_sync(0xffffffffu, s, o);
    __syncthreads();                 // all reads of bval(max)/red done
    if (lane == 0) red[warp] = s;
    __syncthreads();
    if (t == 0) bval = red[0] + red[1] + red[2] + red[3];
    __syncthreads();
    const float inv = 1.f / bval;

    float* dst = g_w + (size_t)h * I_DIM * I_DIM + i;   // [h][j][i]
    dst[(size_t)t * I_DIM]         = e0 * inv;
    dst[(size_t)(t + 128) * I_DIM] = e1 * inv;
    dst[(size_t)(t + 256) * I_DIM] = e2 * inv;
}

// ---------------------------------------------------------------------------
// K4: per (s, 32-wide i tile): weights = sum_j w[h][j][i] * v[s][j][hc],
//     o = gate * weights, out = o @ W_out.  256 thr, warp==head, 4x8 reg tile.
// SMEM (dynamic): v_sh/o_sh [32][260] at 0 ; w_sh [8][32][32] at 8320 ;
//                 Wout_sh [256][64] at 8320 (after loop, overlaps w_sh).
// ---------------------------------------------------------------------------
__global__ __launch_bounds__(256) void k4_main(
    const float* __restrict__ Wout, float* __restrict__ outp)
{
    extern __shared__ float sm[];
    float* v_sh    = sm;           // 32*260 = 8320 floats (also o_sh)
    float* w_sh    = sm + 8320;    // 8192 floats
    float* Wout_sh = sm + 8320;    // 16384 floats (used after main loop)

    const int t    = threadIdx.x;
    const int lane = t & 31;
    const int h    = t >> 5;                 // warp == head
    const int i0   = blockIdx.x * 32;
    const int s    = blockIdx.y;
    const int ii0  = (lane >> 2) * 4;        // 8 groups of 4 rows
    const int c0   = (lane & 3) * 8;         // 4 groups of 8 channels

    float acc[4][8];
    #pragma unroll
    for (int a = 0; a < 4; a++)
        #pragma unroll
        for (int b = 0; b < 8; b++) acc[a][b] = 0.f;

    for (int j0 = 0; j0 < I_DIM; j0 += 32) {
        __syncthreads();   // previous tile fully consumed
        {   // v tile: 2048 float4, coalesced; dest rows padded to 260 floats
            const float4* src = (const float4*)(g_v + ((size_t)s * I_DIM + j0) * HC);
            #pragma unroll
            for (int u = 0; u < 8; u++) {
                int lin = t + 256 * u;          // 0..2047 (float4 units)
                int jj = lin >> 6, q = lin & 63;
                ((float4*)(v_sh + jj * 260))[q] = src[jj * 64 + q];
            }
        }
        {   // w tile: w_sh[h][jj][ii] from g_w[h][j0+jj][i0+ii] (coalesced in ii)
            #pragma unroll
            for (int u = 0; u < 8; u++) {
                int lin = t + 256 * u;          // 0..2047 (float4 units)
                int iq = lin & 7, jj = (lin >> 3) & 31, hh = lin >> 8;
                const float4* src =
                    (const float4*)(g_w + ((size_t)hh * I_DIM + j0 + jj) * I_DIM + i0);
                ((float4*)(w_sh + (hh * 32 + jj) * 32))[iq] = src[iq];
            }
        }
        __syncthreads();

        const float* wp = w_sh + h * 1024;
        #pragma unroll 4
        for (int jj = 0; jj < 32; jj++) {
            float4 wq = *(const float4*)(wp + jj * 32 + ii0);
            float4 va = *(const float4*)(v_sh + jj * 260 + h * 32 + c0);
            float4 vb = *(const float4*)(v_sh + jj * 260 + h * 32 + c0 + 4);
            float wr[4] = {wq.x, wq.y, wq.z, wq.w};
            float vr[8] = {va.x, va.y, va.z, va.w, vb.x, vb.y, vb.z, vb.w};
            #pragma unroll
            for (int a = 0; a < 4; a++)
                #pragma unroll
                for (int b = 0; b < 8; b++) acc[a][b] += wr[a] * vr[b];
        }
    }
    __syncthreads();   // done with v_sh / w_sh

    {   // load W_out into SMEM (4096 float4) — overlaps w_sh region
        const float4* src = (const float4*)Wout;
        float4* dst = (float4*)Wout_sh;
        #pragma unroll
        for (int u = 0; u < 16; u++) dst[t + 256 * u] = src[t + 256 * u];
    }
    {   // gate multiply, stage o into v_sh region
        #pragma unroll
        for (int a = 0; a < 4; a++) {
            const int ii = ii0 + a;
            const float* gp = g_gate + ((size_t)s * I_DIM + i0 + ii) * HC + h * 32 + c0;
            float4 ga = *(const float4*)gp;
            float4 gb = *(const float4*)(gp + 4);
            float4 oa = make_float4(ga.x * acc[a][0], ga.y * acc[a][1],
                                    ga.z * acc[a][2], ga.w * acc[a][3]);
            float4 ob = make_float4(gb.x * acc[a][4], gb.y * acc[a][5],
                                    gb.z * acc[a][6], gb.w * acc[a][7]);
            *(float4*)(v_sh + ii * 260 + h * 32 + c0)     = oa;
            *(float4*)(v_sh + ii * 260 + h * 32 + c0 + 4) = ob;
        }
    }
    __syncthreads();

    {   // projection: out[ii][d] = sum_hc o[ii][hc] * Wout[hc][d]
        const int iiA = (t >> 4) * 2;
        const int d0  = (t & 15) * 4;
        float a0[4] = {0, 0, 0, 0}, a1[4] = {0, 0, 0, 0};
        #pragma unroll 8
        for (int k = 0; k < 256; k++) {
            float o0 = v_sh[iiA * 260 + k];
            float o1 = v_sh[(iiA + 1) * 260 + k];
            float4 wf = *(const float4*)(Wout_sh + k * 64 + d0);
            a0[0] += o0 * wf.x; a0[1] += o0 * wf.y; a0[2] += o0 * wf.z; a0[3] += o0 * wf.w;
            a1[0] += o1 * wf.x; a1[1] += o1 * wf.y; a1[2] += o1 * wf.z; a1[3] += o1 * wf.w;
        }
        float* op = outp + ((size_t)s * I_DIM + i0 + iiA) * CM + d0;
        *(float4*)op        = make_float4(a0[0], a0[1], a0[2], a0[3]);
        *(float4*)(op + CM) = make_float4(a1[0], a1[1], a1[2], a1[3]);
    }
}

// ---------------------------------------------------------------------------
extern "C" void kernel_launch(void* const* d_in, const int* in_sizes, int n_in,
                              void* d_out, int out_size)
{
    (void)in_sizes; (void)n_in; (void)out_size;
    const float* msa  = (const float*)d_in[0];
    const float* pair = (const float*)d_in[1];
    const float* lmg  = (const float*)d_in[2];
    const float* lmb  = (const float*)d_in[3];
    const float* lpg  = (const float*)d_in[4];
    const float* lpb  = (const float*)d_in[5];
    const float* Wv   = (const float*)d_in[6];
    const float* Wb   = (const float*)d_in[7];
    const float* Wg   = (const float*)d_in[8];
    const float* Wo   = (const float*)d_in[9];
    float* outp = (float*)d_out;

    cudaFuncSetAttribute(k1_v_gate, cudaFuncAttributeMaxDynamicSharedMemorySize, 69632);
    cudaFuncSetAttribute(k4_main,   cudaFuncAttributeMaxDynamicSharedMemorySize, 98816);

    k1_v_gate<<<(S_DIM * I_DIM) / 16, 256, 69632>>>(msa, lmg, lmb, Wv, Wg);
    k2_bias<<<I_DIM * I_DIM, 128>>>(pair, lpg, lpb, Wb);
    k3_softmax<<<I_DIM * H_DIM, 128>>>();
    k4_main<<<dim3(I_DIM / 32, S_DIM), 256, 98816>>>(Wo, outp);
}

// round 4
// speedup vs baseline: 1.5767x; 1.5767x over previous
#include <cuda_runtime.h>
#include <cstdint>

// MSAPairWeightedAverage — round 3: einsum via mma.sync tf32 (tcgen05 is
// ptxas-rejected on this toolchain's sm_103 target).
// S=512, I=384, C_MSA=64, C_Z=128, H=8, C=32 (H*C=256)

#define S_DIM 512
#define I_DIM 384
#define CM    64
#define CZ    128
#define H_DIM 8
#define HC    256
#define LN_EPS 1e-5f

// Scratch (__device__ globals; allocation-free rule)
__device__ float g_v[(size_t)H_DIM * S_DIM * 32 * I_DIM];   // [h][n=s*32+c][j]  (K-major B)
__device__ float g_gate[(size_t)S_DIM * I_DIM * HC];        // [s][i][hc]
__device__ float g_wt[(size_t)S_DIM * I_DIM * HC];          // [s][i][hc] gate*weights
__device__ float g_bias[(size_t)I_DIM * H_DIM * I_DIM];     // [i][h][j]
__device__ float g_w[(size_t)H_DIM * I_DIM * I_DIM];        // [h][i][j]  (K-major A)

// ---------------------------------------------------------------------------
__device__ __forceinline__ float f2tf32(float x) {
    uint32_t r;
    asm("cvt.rna.tf32.f32 %0, %1;" : "=r"(r) : "f"(x));
    return __uint_as_float(r);
}
__device__ __forceinline__ void cp_async16(uint32_t dst, const void* src) {
    asm volatile("cp.async.cg.shared.global [%0], [%1], 16;" :: "r"(dst), "l"(src));
}
__device__ __forceinline__ void cp_commit() { asm volatile("cp.async.commit_group;" ::: "memory"); }
__device__ __forceinline__ void cp_wait1()  { asm volatile("cp.async.wait_group 1;"  ::: "memory"); }
__device__ __forceinline__ void cp_wait0()  { asm volatile("cp.async.wait_group 0;"  ::: "memory"); }
__device__ __forceinline__ uint32_t smem_u32(const void* p) {
    uint32_t a;
    asm("{ .reg .u64 t; cvta.to.shared.u64 t, %1; cvt.u32.u64 %0, t; }" : "=r"(a) : "l"(p));
    return a;
}
// SW128 swizzle on 128B rows: float4 slot q -> q ^ (row&7)
__device__ __forceinline__ uint32_t swz128(uint32_t off) { return off ^ ((off >> 3) & 0x70); }
__device__ __forceinline__ uint32_t swq(int row, int q, int c) {
    return (uint32_t)(row * 128 + ((q ^ (row & 7)) << 4) + (c << 2));
}

__device__ __forceinline__ void mma_tf32(float* d, const uint32_t* a, const uint32_t* b) {
    asm volatile(
        "mma.sync.aligned.m16n8k8.row.col.f32.tf32.tf32.f32 "
        "{%0,%1,%2,%3}, {%4,%5,%6,%7}, {%8,%9}, {%0,%1,%2,%3};"
        : "+f"(d[0]), "+f"(d[1]), "+f"(d[2]), "+f"(d[3])
        : "r"(a[0]), "r"(a[1]), "r"(a[2]), "r"(a[3]), "r"(b[0]), "r"(b[1]));
}

// ---------------------------------------------------------------------------
// K1: LN(msa); v = msa_n @ W_v -> g_v (tf32-rounded); gate = sigmoid(msa_n @ W_gate)
// ---------------------------------------------------------------------------
__global__ __launch_bounds__(256) void k1_v_gate(
    const float* __restrict__ msa,
    const float* __restrict__ ln_g, const float* __restrict__ ln_b,
    const float* __restrict__ Wv,   const float* __restrict__ Wg)
{
    extern __shared__ float sm[];
    float* Wsh   = sm;               // 64*256
    float* msa_t = sm + 64 * 256;    // [64][16]

    const int t    = threadIdx.x;
    const int lane = t & 31;
    const int warp = t >> 5;
    const int rb   = blockIdx.x * 16;
    const int s_idx = rb / I_DIM;
    const int ib    = rb - s_idx * I_DIM;       // j base (multiple of 16)

    #pragma unroll
    for (int rr = 0; rr < 2; rr++) {
        const int r = warp * 2 + rr;
        const float* x = msa + (size_t)(rb + r) * CM;
        float x0 = x[lane], x1 = x[lane + 32];
        float s = x0 + x1, s2 = x0 * x0 + x1 * x1;
        #pragma unroll
        for (int o = 16; o; o >>= 1) {
            s  += __shfl_xor_sync(0xffffffffu, s,  o);
            s2 += __shfl_xor_sync(0xffffffffu, s2, o);
        }
        float mu  = s * (1.f / 64.f);
        float var = s2 * (1.f / 64.f) - mu * mu;
        float rs  = rsqrtf(var + LN_EPS);
        msa_t[lane * 16 + r]        = (x0 - mu) * rs * ln_g[lane]      + ln_b[lane];
        msa_t[(lane + 32) * 16 + r] = (x1 - mu) * rs * ln_g[lane + 32] + ln_b[lane + 32];
    }

    for (int phase = 0; phase < 2; phase++) {
        const float* W = phase ? Wg : Wv;
        __syncthreads();
        {
            const float4* src = (const float4*)W;
            float4* dst = (float4*)Wsh;
            #pragma unroll
            for (int u = 0; u < 16; u++) dst[t + 256 * u] = src[t + 256 * u];
        }
        __syncthreads();

        float acc[16];
        #pragma unroll
        for (int r = 0; r < 16; r++) acc[r] = 0.f;

        #pragma unroll 8
        for (int k = 0; k < 64; k++) {
            float wv = Wsh[k * 256 + t];
            const float4* m4 = (const float4*)(msa_t + k * 16);
            float4 m0 = m4[0], m1 = m4[1], m2 = m4[2], m3 = m4[3];
            acc[0]  += m0.x * wv; acc[1]  += m0.y * wv; acc[2]  += m0.z * wv; acc[3]  += m0.w * wv;
            acc[4]  += m1.x * wv; acc[5]  += m1.y * wv; acc[6]  += m1.z * wv; acc[7]  += m1.w * wv;
            acc[8]  += m2.x * wv; acc[9]  += m2.y * wv; acc[10] += m2.z * wv; acc[11] += m2.w * wv;
            acc[12] += m3.x * wv; acc[13] += m3.y * wv; acc[14] += m3.z * wv; acc[15] += m3.w * wv;
        }

        if (phase == 0) {
            // v -> [h][s*32+c][j]; thread t: h = t>>5, c = t&31, 16 consecutive j
            float* vp = g_v + (((size_t)(t >> 5) * S_DIM + s_idx) * 32 + (t & 31)) * I_DIM + ib;
            float4* vp4 = (float4*)vp;
            vp4[0] = make_float4(f2tf32(acc[0]),  f2tf32(acc[1]),  f2tf32(acc[2]),  f2tf32(acc[3]));
            vp4[1] = make_float4(f2tf32(acc[4]),  f2tf32(acc[5]),  f2tf32(acc[6]),  f2tf32(acc[7]));
            vp4[2] = make_float4(f2tf32(acc[8]),  f2tf32(acc[9]),  f2tf32(acc[10]), f2tf32(acc[11]));
            vp4[3] = make_float4(f2tf32(acc[12]), f2tf32(acc[13]), f2tf32(acc[14]), f2tf32(acc[15]));
        } else {
            #pragma unroll
            for (int r = 0; r < 16; r++) {
                float val = 1.f / (1.f + __expf(-acc[r]));
                g_gate[(size_t)(rb + r) * HC + t] = val;
            }
        }
    }
}

// ---------------------------------------------------------------------------
// K2: bias[i][h][j] = LN(pair[i][j]) @ W_bias
// ---------------------------------------------------------------------------
__global__ __launch_bounds__(128) void k2_bias(
    const float* __restrict__ pair,
    const float* __restrict__ gz, const float* __restrict__ bz,
    const float* __restrict__ Wb)
{
    __shared__ float red[8];
    __shared__ float stats[2];
    __shared__ float hacc[4][8];

    const int t = threadIdx.x;
    const int lane = t & 31, warp = t >> 5;
    const int row = blockIdx.x;
    const int i = row / I_DIM, j = row - i * I_DIM;

    float x = pair[(size_t)row * CZ + t];
    float s = x, s2 = x * x;
    #pragma unroll
    for (int o = 16; o; o >>= 1) {
        s  += __shfl_xor_sync(0xffffffffu, s,  o);
        s2 += __shfl_xor_sync(0xffffffffu, s2, o);
    }
    if (lane == 0) { red[warp] = s; red[warp + 4] = s2; }
    __syncthreads();
    if (t == 0) {
        float ts  = red[0] + red[1] + red[2] + red[3];
        float ts2 = red[4] + red[5] + red[6] + red[7];
        float mu  = ts * (1.f / 128.f);
        float var = ts2 * (1.f / 128.f) - mu * mu;
        stats[0] = mu; stats[1] = rsqrtf(var + LN_EPS);
    }
    __syncthreads();
    float xn = (x - stats[0]) * stats[1] * gz[t] + bz[t];

    const float4* wb4 = (const float4*)(Wb + t * 8);
    float4 wa = wb4[0], wbv = wb4[1];
    float p[8];
    p[0] = xn * wa.x;  p[1] = xn * wa.y;  p[2] = xn * wa.z;  p[3] = xn * wa.w;
    p[4] = xn * wbv.x; p[5] = xn * wbv.y; p[6] = xn * wbv.z; p[7] = xn * wbv.w;
    #pragma unroll
    for (int h = 0; h < 8; h++) {
        #pragma unroll
        for (int o = 16; o; o >>= 1) p[h] += __shfl_xor_sync(0xffffffffu, p[h], o);
    }
    if (lane == 0) {
        #pragma unroll
        for (int h = 0; h < 8; h++) hacc[warp][h] = p[h];
    }
    __syncthreads();
    if (t < 8) {
        float sum = hacc[0][t] + hacc[1][t] + hacc[2][t] + hacc[3][t];
        g_bias[((size_t)i * H_DIM + t) * I_DIM + j] = sum;
    }
}

// ---------------------------------------------------------------------------
// K3: w[h][i][j] = softmax_j(bias[i][h][j])  (tf32-rounded stores)
// ---------------------------------------------------------------------------
__global__ __launch_bounds__(128) void k3_softmax()
{
    __shared__ float red[4];
    __shared__ float bval;

    const int t = threadIdx.x;
    const int lane = t & 31, warp = t >> 5;
    const int b = blockIdx.x;
    const int i = b >> 3, h = b & 7;

    const float* src = g_bias + ((size_t)i * H_DIM + h) * I_DIM;
    float x0 = src[t], x1 = src[t + 128], x2 = src[t + 256];

    float m = fmaxf(x0, fmaxf(x1, x2));
    #pragma unroll
    for (int o = 16; o; o >>= 1) m = fmaxf(m, __shfl_xor_sync(0xffffffffu, m, o));
    if (lane == 0) red[warp] = m;
    __syncthreads();
    if (t == 0) bval = fmaxf(fmaxf(red[0], red[1]), fmaxf(red[2], red[3]));
    __syncthreads();
    const float mx = bval;

    float e0 = __expf(x0 - mx), e1 = __expf(x1 - mx), e2 = __expf(x2 - mx);
    float s = e0 + e1 + e2;
    #pragma unroll
    for (int o = 16; o; o >>= 1) s += __shfl_xor_sync(0xffffffffu, s, o);
    __syncthreads();
    if (lane == 0) red[warp] = s;
    __syncthreads();
    if (t == 0) bval = red[0] + red[1] + red[2] + red[3];
    __syncthreads();
    const float inv = 1.f / bval;

    float* dst = g_w + ((size_t)h * I_DIM + i) * I_DIM;   // [h][i][j]
    dst[t]       = f2tf32(e0 * inv);
    dst[t + 128] = f2tf32(e1 * inv);
    dst[t + 256] = f2tf32(e2 * inv);
}

// ---------------------------------------------------------------------------
// K4: mma.sync tf32 GEMM per head:  D[i, n] = sum_j w[h][i][j] * v[h][n][j]
// Block 128x128, 8 warps (4m x 2n), warp tile 32x64, K chunks of 32, 2-stage.
// Epilogue fuses gate multiply -> g_wt[s][i][hc].
// SMEM: A0 @0, A1 @16K, B0 @32K, B1 @48K  (total 64KB)
// ---------------------------------------------------------------------------
__global__ __launch_bounds__(256) void k4_gemm()
{
    extern __shared__ char smc[];
    const uint32_t sb = smem_u32(smc);

    const int t    = threadIdx.x;
    const int lane = t & 31;
    const int warp = t >> 5;
    const int wm   = warp >> 1;        // 0..3
    const int wn   = warp & 1;         // 0..1
    const int r    = lane >> 2;        // 0..7
    const int cq   = lane & 3;         // 0..3

    const int n0 = blockIdx.x * 128;
    const int i0 = blockIdx.y * 128;
    const int h  = blockIdx.z;

    const float* Ag = g_w + ((size_t)h * I_DIM + i0) * I_DIM;
    const float* Bg = g_v + ((size_t)h * 16384 + n0) * I_DIM;

    float acc[2][8][4];
    #pragma unroll
    for (int mt = 0; mt < 2; mt++)
        #pragma unroll
        for (int nt = 0; nt < 8; nt++)
            #pragma unroll
            for (int e = 0; e < 4; e++) acc[mt][nt][e] = 0.f;

    // chunk loader: A/B 128 rows x 32 floats, SW128-swizzled, 16B cp.async
    auto LOAD = [&](int kc, int buf) {
        const uint32_t Ab = sb + buf * 16384;
        const uint32_t Bb = sb + 32768 + buf * 16384;
        const int k0 = kc * 32;
        #pragma unroll
        for (int u = 0; u < 4; u++) {
            int lin = u * 256 + t;
            int row = lin >> 3, q = lin & 7;
            cp_async16(Ab + swz128(row * 128 + q * 16),
                       Ag + (size_t)row * I_DIM + k0 + q * 4);
        }
        #pragma unroll
        for (int u = 0; u < 4; u++) {
            int lin = u * 256 + t;
            int row = lin >> 3, q = lin & 7;
            cp_async16(Bb + swz128(row * 128 + q * 16),
                       Bg + (size_t)row * I_DIM + k0 + q * 4);
        }
        cp_commit();
    };

    LOAD(0, 0);

    #pragma unroll 1
    for (int kc = 0; kc < 12; kc++) {
        const int buf = kc & 1;
        if (kc < 11) { LOAD(kc + 1, buf ^ 1); cp_wait1(); }
        else         { cp_wait0(); }
        __syncthreads();

        const char* Ab = smc + buf * 16384;
        const char* Bb = smc + 32768 + buf * 16384;

        #pragma unroll
        for (int ks = 0; ks < 4; ks++) {
            const int q0 = ks * 2, q1 = ks * 2 + 1;
            uint32_t a[2][4];
            #pragma unroll
            for (int mt = 0; mt < 2; mt++) {
                const int row0 = wm * 32 + mt * 16 + r;
                const int row1 = row0 + 8;
                a[mt][0] = *(const uint32_t*)(Ab + swq(row0, q0, cq));
                a[mt][1] = *(const uint32_t*)(Ab + swq(row1, q0, cq));
                a[mt][2] = *(const uint32_t*)(Ab + swq(row0, q1, cq));
                a[mt][3] = *(const uint32_t*)(Ab + swq(row1, q1, cq));
            }
            uint32_t b[8][2];
            #pragma unroll
            for (int nt = 0; nt < 8; nt++) {
                const int rown = wn * 64 + nt * 8 + r;
                b[nt][0] = *(const uint32_t*)(Bb + swq(rown, q0, cq));
                b[nt][1] = *(const uint32_t*)(Bb + swq(rown, q1, cq));
            }
            #pragma unroll
            for (int mt = 0; mt < 2; mt++)
                #pragma unroll
                for (int nt = 0; nt < 8; nt++)
                    mma_tf32(acc[mt][nt], a[mt], b[nt]);
        }
        __syncthreads();
    }

    // Epilogue: d(row, col): c0/c1 = (r, 2cq)/(r, 2cq+1); c2/c3 at row+8.
    #pragma unroll
    for (int mt = 0; mt < 2; mt++) {
        #pragma unroll
        for (int nt = 0; nt < 8; nt++) {
            const int n_lo = n0 + wn * 64 + nt * 8 + 2 * cq;
            const int s = n_lo >> 5, c = n_lo & 31;
            const int i = i0 + wm * 32 + mt * 16 + r;
            const size_t base0 = ((size_t)s * I_DIM + i) * HC + h * 32 + c;
            const size_t base1 = base0 + (size_t)8 * HC;
            float2 g0 = *(const float2*)(g_gate + base0);
            float2 g1 = *(const float2*)(g_gate + base1);
            float2 o0, o1;
            o0.x = g0.x * acc[mt][nt][0];
            o0.y = g0.y * acc[mt][nt][1];
            o1.x = g1.x * acc[mt][nt][2];
            o1.y = g1.y * acc[mt][nt][3];
            *(float2*)(g_wt + base0) = o0;
            *(float2*)(g_wt + base1) = o1;
        }
    }
}

// ---------------------------------------------------------------------------
// K5: out = g_wt @ W_out   ([196608 x 256] @ [256 x 64])
// ---------------------------------------------------------------------------
__global__ __launch_bounds__(128) void k5_out(
    const float* __restrict__ Wout, float* __restrict__ outp)
{
    extern __shared__ float sm[];
    float* Wsh = sm;            // 256*64
    float* Osh = sm + 16384;    // 32*256

    const int t  = threadIdx.x;
    const int rb = blockIdx.x * 32;

    {
        const float4* src = (const float4*)Wout;
        float4* dst = (float4*)Wsh;
        #pragma unroll
        for (int u = 0; u < 32; u++) dst[u * 128 + t] = src[u * 128 + t];
    }
    {
        const float4* src = (const float4*)(g_wt + (size_t)rb * HC);
        float4* dst = (float4*)Osh;
        #pragma unroll
        for (int u = 0; u < 16; u++) dst[u * 128 + t] = src[u * 128 + t];
    }
    __syncthreads();

    const int rg = t >> 4;
    const int cg = t & 15;
    float acc[4][4];
    #pragma unroll
    for (int a = 0; a < 4; a++)
        #pragma unroll
        for (int b = 0; b < 4; b++) acc[a][b] = 0.f;

    const float* o0 = Osh + (rg * 4) * 256;
    #pragma unroll 4
    for (int k = 0; k < 256; k++) {
        float4 wv = *(const float4*)(Wsh + k * 64 + cg * 4);
        float a = o0[k], b = o0[256 + k], c = o0[512 + k], d = o0[768 + k];
        acc[0][0] += a * wv.x; acc[0][1] += a * wv.y; acc[0][2] += a * wv.z; acc[0][3] += a * wv.w;
        acc[1][0] += b * wv.x; acc[1][1] += b * wv.y; acc[1][2] += b * wv.z; acc[1][3] += b * wv.w;
        acc[2][0] += c * wv.x; acc[2][1] += c * wv.y; acc[2][2] += c * wv.z; acc[2][3] += c * wv.w;
        acc[3][0] += d * wv.x; acc[3][1] += d * wv.y; acc[3][2] += d * wv.z; acc[3][3] += d * wv.w;
    }

    float* op = outp + (size_t)(rb + rg * 4) * CM + cg * 4;
    #pragma unroll
    for (int r = 0; r < 4; r++)
        *(float4*)(op + (size_t)r * CM) =
            make_float4(acc[r][0], acc[r][1], acc[r][2], acc[r][3]);
}

// ---------------------------------------------------------------------------
extern "C" void kernel_launch(void* const* d_in, const int* in_sizes, int n_in,
                              void* d_out, int out_size)
{
    (void)in_sizes; (void)n_in; (void)out_size;
    const float* msa  = (const float*)d_in[0];
    const float* pair = (const float*)d_in[1];
    const float* lmg  = (const float*)d_in[2];
    const float* lmb  = (const float*)d_in[3];
    const float* lpg  = (const float*)d_in[4];
    const float* lpb  = (const float*)d_in[5];
    const float* Wv   = (const float*)d_in[6];
    const float* Wb   = (const float*)d_in[7];
    const float* Wg   = (const float*)d_in[8];
    const float* Wo   = (const float*)d_in[9];
    float* outp = (float*)d_out;

    cudaFuncSetAttribute(k1_v_gate, cudaFuncAttributeMaxDynamicSharedMemorySize, 69632);
    cudaFuncSetAttribute(k4_gemm,   cudaFuncAttributeMaxDynamicSharedMemorySize, 65536);
    cudaFuncSetAttribute(k5_out,    cudaFuncAttributeMaxDynamicSharedMemorySize, 98304);

    k1_v_gate<<<(S_DIM * I_DIM) / 16, 256, 69632>>>(msa, lmg, lmb, Wv, Wg);
    k2_bias<<<I_DIM * I_DIM, 128>>>(pair, lpg, lpb, Wb);
    k3_softmax<<<I_DIM * H_DIM, 128>>>();
    k4_gemm<<<dim3(128, 3, 8), 256, 65536>>>();
    k5_out<<<(S_DIM * I_DIM) / 32, 128, 98304>>>(Wo, outp);
}

// round 5
// speedup vs baseline: 2.6828x; 1.7016x over previous
#include <cuda_runtime.h>
#include <cstdint>

// MSAPairWeightedAverage — round 5: all three big GEMMs on mma.sync tf32.
// S=512, I=384, C_MSA=64, C_Z=128, H=8, C=32 (H*C=256)

#define S_DIM 512
#define I_DIM 384
#define CM    64
#define CZ    128
#define H_DIM 8
#define HC    256
#define LN_EPS 1e-5f

// Scratch (__device__ globals; allocation-free rule)
__device__ float g_v[(size_t)H_DIM * S_DIM * 32 * I_DIM];   // [h][n=s*32+c][j]  (K-major B)
__device__ float g_gate[(size_t)S_DIM * I_DIM * HC];        // [s][i][hc]
__device__ float g_wt[(size_t)S_DIM * I_DIM * HC];          // [s][i][hc] gate*weights (tf32)
__device__ float g_bias[(size_t)I_DIM * H_DIM * I_DIM];     // [i][h][j]
__device__ float g_w[(size_t)H_DIM * I_DIM * I_DIM];        // [h][i][j]  (K-major A)
__device__ float g_wvt[256 * 64];                           // Wv^T  [n=256][k=64]  swizzled tf32
__device__ float g_wgt[256 * 64];                           // Wg^T  swizzled tf32
__device__ float g_wot[64 * 256];                           // Wout^T [n=64][k=256] swizzled tf32

// ---------------------------------------------------------------------------
__device__ __forceinline__ float f2tf32(float x) {
    uint32_t r;
    asm("cvt.rna.tf32.f32 %0, %1;" : "=r"(r) : "f"(x));
    return __uint_as_float(r);
}
__device__ __forceinline__ void cp_async16(uint32_t dst, const void* src) {
    asm volatile("cp.async.cg.shared.global [%0], [%1], 16;" :: "r"(dst), "l"(src));
}
__device__ __forceinline__ void cp_commit() { asm volatile("cp.async.commit_group;" ::: "memory"); }
__device__ __forceinline__ void cp_wait1()  { asm volatile("cp.async.wait_group 1;"  ::: "memory"); }
__device__ __forceinline__ void cp_wait0()  { asm volatile("cp.async.wait_group 0;"  ::: "memory"); }
__device__ __forceinline__ uint32_t smem_u32(const void* p) {
    uint32_t a;
    asm("{ .reg .u64 t; cvta.to.shared.u64 t, %1; cvt.u32.u64 %0, t; }" : "=r"(a) : "l"(p));
    return a;
}
// 128B-row SW swizzle (k4-proven)
__device__ __forceinline__ uint32_t swz128(uint32_t off) { return off ^ ((off >> 3) & 0x70); }
// generic: byte offset of element (row, k) in a row of rowBytes, 16B-granule XOR-swizzled
__device__ __forceinline__ uint32_t bo(int row, int k, int rowBytes) {
    return (uint32_t)(row * rowBytes + ((((k >> 2) ^ (row & 7)) << 4) | ((k & 3) << 2)));
}

__device__ __forceinline__ void mma_tf32(float* d, const uint32_t* a, const uint32_t* b) {
    asm volatile(
        "mma.sync.aligned.m16n8k8.row.col.f32.tf32.tf32.f32 "
        "{%0,%1,%2,%3}, {%4,%5,%6,%7}, {%8,%9}, {%0,%1,%2,%3};"
        : "+f"(d[0]), "+f"(d[1]), "+f"(d[2]), "+f"(d[3])
        : "r"(a[0]), "r"(a[1]), "r"(a[2]), "r"(a[3]), "r"(b[0]), "r"(b[1]));
}

// ---------------------------------------------------------------------------
// K0: prep transposed, tf32-rounded, pre-swizzled weights. One block, 256 thr.
// ---------------------------------------------------------------------------
__global__ __launch_bounds__(256) void k0_prep(
    const float* __restrict__ Wv, const float* __restrict__ Wg,
    const float* __restrict__ Wo)
{
    const int t = threadIdx.x;
    // Wv^T / Wg^T: [n=256][k=64], rowBytes 256.  thread t = row n.
    #pragma unroll 4
    for (int k = 0; k < 64; k++) {
        uint32_t idx = bo(t, k, 256) >> 2;
        g_wvt[idx] = f2tf32(Wv[k * 256 + t]);
        g_wgt[idx] = f2tf32(Wg[k * 256 + t]);
    }
    // Wout^T: [n=64][k=256], rowBytes 1024. thread t: n = t&63, k block (t>>6)*64.
    const int n = t & 63, kb = (t >> 6) * 64;
    #pragma unroll 4
    for (int kk = 0; kk < 64; kk++) {
        const int k = kb + kk;
        g_wot[bo(n, k, 1024) >> 2] = f2tf32(Wo[k * 64 + n]);
    }
}

// ---------------------------------------------------------------------------
// K1: LN(msa) -> A smem (tf32); v = A @ Wv (to g_v K-major), gate = sigmoid(A @ Wg).
// Block: 128 rows, 8 warps (4m x 2n), warp tile 32x64, two n-halves, two phases.
// SMEM: Ash [128][64] 32KB @0 ; Wsh [256][64] 64KB @32KB.  Total 96KB.
// ---------------------------------------------------------------------------
__global__ __launch_bounds__(256) void k1_v_gate(
    const float* __restrict__ msa,
    const float* __restrict__ ln_g, const float* __restrict__ ln_b)
{
    extern __shared__ char smc[];
    char* Ash = smc;
    char* Wsh = smc + 32768;

    const int t    = threadIdx.x;
    const int lane = t & 31;
    const int warp = t >> 5;
    const int wm   = warp >> 1;      // 0..3
    const int wn   = warp & 1;       // 0..1
    const int r    = lane >> 2;      // 0..7
    const int cq   = lane & 3;       // 0..3

    const int rb    = blockIdx.x * 128;
    const int s_idx = rb / I_DIM;
    const int j0    = rb - s_idx * I_DIM;   // multiple of 128

    // LayerNorm: each warp 16 rows; store tf32 into swizzled Ash.
    const float lg0 = ln_g[lane], lg1 = ln_g[lane + 32];
    const float lb0 = ln_b[lane], lb1 = ln_b[lane + 32];
    #pragma unroll 4
    for (int rr = 0; rr < 16; rr++) {
        const int row = warp * 16 + rr;
        const float* x = msa + (size_t)(rb + row) * CM;
        float x0 = x[lane], x1 = x[lane + 32];
        float s = x0 + x1, s2 = x0 * x0 + x1 * x1;
        #pragma unroll
        for (int o = 16; o; o >>= 1) {
            s  += __shfl_xor_sync(0xffffffffu, s,  o);
            s2 += __shfl_xor_sync(0xffffffffu, s2, o);
        }
        float mu  = s * (1.f / 64.f);
        float var = s2 * (1.f / 64.f) - mu * mu;
        float rs  = rsqrtf(var + LN_EPS);
        *(float*)(Ash + bo(row, lane,      256)) = f2tf32((x0 - mu) * rs * lg0 + lb0);
        *(float*)(Ash + bo(row, lane + 32, 256)) = f2tf32((x1 - mu) * rs * lg1 + lb1);
    }

    for (int p = 0; p < 2; p++) {
        __syncthreads();   // A ready / previous phase's Wsh reads done
        {   // Wsh <- pre-swizzled W^T (straight copy, 4096 float4)
            const float4* src = (const float4*)(p ? g_wgt : g_wvt);
            float4* dst = (float4*)Wsh;
            #pragma unroll
            for (int u = 0; u < 16; u++) dst[u * 256 + t] = src[u * 256 + t];
        }
        __syncthreads();

        for (int nh = 0; nh < 2; nh++) {
            float acc[2][8][4];
            #pragma unroll
            for (int mt = 0; mt < 2; mt++)
                #pragma unroll
                for (int nt = 0; nt < 8; nt++)
                    #pragma unroll
                    for (int e = 0; e < 4; e++) acc[mt][nt][e] = 0.f;

            #pragma unroll
            for (int ks = 0; ks < 8; ks++) {
                const int klo = ks * 8 + cq, khi = klo + 4;
                uint32_t a[2][4];
                #pragma unroll
                for (int mt = 0; mt < 2; mt++) {
                    const int row0 = wm * 32 + mt * 16 + r;
                    a[mt][0] = *(const uint32_t*)(Ash + bo(row0,     klo, 256));
                    a[mt][1] = *(const uint32_t*)(Ash + bo(row0 + 8, klo, 256));
                    a[mt][2] = *(const uint32_t*)(Ash + bo(row0,     khi, 256));
                    a[mt][3] = *(const uint32_t*)(Ash + bo(row0 + 8, khi, 256));
                }
                uint32_t b[8][2];
                #pragma unroll
                for (int nt = 0; nt < 8; nt++) {
                    const int n = nh * 128 + wn * 64 + nt * 8 + r;
                    b[nt][0] = *(const uint32_t*)(Wsh + bo(n, klo, 256));
                    b[nt][1] = *(const uint32_t*)(Wsh + bo(n, khi, 256));
                }
                #pragma unroll
                for (int mt = 0; mt < 2; mt++)
                    #pragma unroll
                    for (int nt = 0; nt < 8; nt++)
                        mma_tf32(acc[mt][nt], a[mt], b[nt]);
            }

            // epilogue
            #pragma unroll
            for (int mt = 0; mt < 2; mt++) {
                #pragma unroll
                for (int nt = 0; nt < 8; nt++) {
                    const int nc  = nh * 128 + wn * 64 + nt * 8 + 2 * cq;
                    const int row = wm * 32 + mt * 16 + r;
                    if (p == 0) {
                        const int h = nc >> 5, c = nc & 31;
                        const int j = j0 + row;
                        float* base =
                            g_v + ((size_t)h * 16384 + s_idx * 32 + c) * I_DIM + j;
                        base[0]           = f2tf32(acc[mt][nt][0]);
                        base[I_DIM]       = f2tf32(acc[mt][nt][1]);
                        base[8]           = f2tf32(acc[mt][nt][2]);
                        base[I_DIM + 8]   = f2tf32(acc[mt][nt][3]);
                    } else {
                        float* base = g_gate + (size_t)(rb + row) * HC + nc;
                        *(float2*)base = make_float2(
                            1.f / (1.f + __expf(-acc[mt][nt][0])),
                            1.f / (1.f + __expf(-acc[mt][nt][1])));
                        *(float2*)(base + (size_t)8 * HC) = make_float2(
                            1.f / (1.f + __expf(-acc[mt][nt][2])),
                            1.f / (1.f + __expf(-acc[mt][nt][3])));
                    }
                }
            }
        }
    }
}

// ---------------------------------------------------------------------------
// K2: bias[i][h][j] = LN(pair[i][j]) @ W_bias
// ---------------------------------------------------------------------------
__global__ __launch_bounds__(128) void k2_bias(
    const float* __restrict__ pair,
    const float* __restrict__ gz, const float* __restrict__ bz,
    const float* __restrict__ Wb)
{
    __shared__ float red[8];
    __shared__ float stats[2];
    __shared__ float hacc[4][8];

    const int t = threadIdx.x;
    const int lane = t & 31, warp = t >> 5;
    const int row = blockIdx.x;
    const int i = row / I_DIM, j = row - i * I_DIM;

    float x = pair[(size_t)row * CZ + t];
    float s = x, s2 = x * x;
    #pragma unroll
    for (int o = 16; o; o >>= 1) {
        s  += __shfl_xor_sync(0xffffffffu, s,  o);
        s2 += __shfl_xor_sync(0xffffffffu, s2, o);
    }
    if (lane == 0) { red[warp] = s; red[warp + 4] = s2; }
    __syncthreads();
    if (t == 0) {
        float ts  = red[0] + red[1] + red[2] + red[3];
        float ts2 = red[4] + red[5] + red[6] + red[7];
        float mu  = ts * (1.f / 128.f);
        float var = ts2 * (1.f / 128.f) - mu * mu;
        stats[0] = mu; stats[1] = rsqrtf(var + LN_EPS);
    }
    __syncthreads();
    float xn = (x - stats[0]) * stats[1] * gz[t] + bz[t];

    const float4* wb4 = (const float4*)(Wb + t * 8);
    float4 wa = wb4[0], wbv = wb4[1];
    float p[8];
    p[0] = xn * wa.x;  p[1] = xn * wa.y;  p[2] = xn * wa.z;  p[3] = xn * wa.w;
    p[4] = xn * wbv.x; p[5] = xn * wbv.y; p[6] = xn * wbv.z; p[7] = xn * wbv.w;
    #pragma unroll
    for (int h = 0; h < 8; h++) {
        #pragma unroll
        for (int o = 16; o; o >>= 1) p[h] += __shfl_xor_sync(0xffffffffu, p[h], o);
    }
    if (lane == 0) {
        #pragma unroll
        for (int h = 0; h < 8; h++) hacc[warp][h] = p[h];
    }
    __syncthreads();
    if (t < 8) {
        float sum = hacc[0][t] + hacc[1][t] + hacc[2][t] + hacc[3][t];
        g_bias[((size_t)i * H_DIM + t) * I_DIM + j] = sum;
    }
}

// ---------------------------------------------------------------------------
// K3: w[h][i][j] = softmax_j(bias[i][h][j])  (tf32-rounded stores)
// ---------------------------------------------------------------------------
__global__ __launch_bounds__(128) void k3_softmax()
{
    __shared__ float red[4];
    __shared__ float bval;

    const int t = threadIdx.x;
    const int lane = t & 31, warp = t >> 5;
    const int b = blockIdx.x;
    const int i = b >> 3, h = b & 7;

    const float* src = g_bias + ((size_t)i * H_DIM + h) * I_DIM;
    float x0 = src[t], x1 = src[t + 128], x2 = src[t + 256];

    float m = fmaxf(x0, fmaxf(x1, x2));
    #pragma unroll
    for (int o = 16; o; o >>= 1) m = fmaxf(m, __shfl_xor_sync(0xffffffffu, m, o));
    if (lane == 0) red[warp] = m;
    __syncthreads();
    if (t == 0) bval = fmaxf(fmaxf(red[0], red[1]), fmaxf(red[2], red[3]));
    __syncthreads();
    const float mx = bval;

    float e0 = __expf(x0 - mx), e1 = __expf(x1 - mx), e2 = __expf(x2 - mx);
    float s = e0 + e1 + e2;
    #pragma unroll
    for (int o = 16; o; o >>= 1) s += __shfl_xor_sync(0xffffffffu, s, o);
    __syncthreads();
    if (lane == 0) red[warp] = s;
    __syncthreads();
    if (t == 0) bval = red[0] + red[1] + red[2] + red[3];
    __syncthreads();
    const float inv = 1.f / bval;

    float* dst = g_w + ((size_t)h * I_DIM + i) * I_DIM;   // [h][i][j]
    dst[t]       = f2tf32(e0 * inv);
    dst[t + 128] = f2tf32(e1 * inv);
    dst[t + 256] = f2tf32(e2 * inv);
}

// ---------------------------------------------------------------------------
// K4: mma.sync tf32 GEMM per head:  D[i, n] = sum_j w[h][i][j] * v[h][n][j]
// Grid (3, 128, 8): x = mi (fastest -> 3 blocks share B tile), y = n-tile, z = h.
// Block 128x128, 8 warps (4m x 2n), K chunks of 32, 2-stage cp.async.
// Epilogue: gate multiply, tf32-round, -> g_wt.
// ---------------------------------------------------------------------------
__global__ __launch_bounds__(256) void k4_gemm()
{
    extern __shared__ char smc[];
    const uint32_t sb = smem_u32(smc);

    const int t    = threadIdx.x;
    const int lane = t & 31;
    const int warp = t >> 5;
    const int wm   = warp >> 1;
    const int wn   = warp & 1;
    const int r    = lane >> 2;
    const int cq   = lane & 3;

    const int i0 = blockIdx.x * 128;
    const int n0 = blockIdx.y * 128;
    const int h  = blockIdx.z;

    const float* Ag = g_w + ((size_t)h * I_DIM + i0) * I_DIM;
    const float* Bg = g_v + ((size_t)h * 16384 + n0) * I_DIM;

    float acc[2][8][4];
    #pragma unroll
    for (int mt = 0; mt < 2; mt++)
        #pragma unroll
        for (int nt = 0; nt < 8; nt++)
            #pragma unroll
            for (int e = 0; e < 4; e++) acc[mt][nt][e] = 0.f;

    auto LOAD = [&](int kc, int buf) {
        const uint32_t Ab = sb + buf * 16384;
        const uint32_t Bb = sb + 32768 + buf * 16384;
        const int k0 = kc * 32;
        #pragma unroll
        for (int u = 0; u < 4; u++) {
            int lin = u * 256 + t;
            int row = lin >> 3, q = lin & 7;
            cp_async16(Ab + swz128(row * 128 + q * 16),
                       Ag + (size_t)row * I_DIM + k0 + q * 4);
        }
        #pragma unroll
        for (int u = 0; u < 4; u++) {
            int lin = u * 256 + t;
            int row = lin >> 3, q = lin & 7;
            cp_async16(Bb + swz128(row * 128 + q * 16),
                       Bg + (size_t)row * I_DIM + k0 + q * 4);
        }
        cp_commit();
    };

    LOAD(0, 0);

    #pragma unroll 1
    for (int kc = 0; kc < 12; kc++) {
        const int buf = kc & 1;
        if (kc < 11) { LOAD(kc + 1, buf ^ 1); cp_wait1(); }
        else         { cp_wait0(); }
        __syncthreads();

        const char* Ab = smc + buf * 16384;
        const char* Bb = smc + 32768 + buf * 16384;

        #pragma unroll
        for (int ks = 0; ks < 4; ks++) {
            const int klo = ks * 8 + cq, khi = klo + 4;
            uint32_t a[2][4];
            #pragma unroll
            for (int mt = 0; mt < 2; mt++) {
                const int row0 = wm * 32 + mt * 16 + r;
                a[mt][0] = *(const uint32_t*)(Ab + bo(row0,     klo, 128));
                a[mt][1] = *(const uint32_t*)(Ab + bo(row0 + 8, klo, 128));
                a[mt][2] = *(const uint32_t*)(Ab + bo(row0,     khi, 128));
                a[mt][3] = *(const uint32_t*)(Ab + bo(row0 + 8, khi, 128));
            }
            uint32_t b[8][2];
            #pragma unroll
            for (int nt = 0; nt < 8; nt++) {
                const int rown = wn * 64 + nt * 8 + r;
                b[nt][0] = *(const uint32_t*)(Bb + bo(rown, klo, 128));
                b[nt][1] = *(const uint32_t*)(Bb + bo(rown, khi, 128));
            }
            #pragma unroll
            for (int mt = 0; mt < 2; mt++)
                #pragma unroll
                for (int nt = 0; nt < 8; nt++)
                    mma_tf32(acc[mt][nt], a[mt], b[nt]);
        }
        __syncthreads();
    }

    #pragma unroll
    for (int mt = 0; mt < 2; mt++) {
        #pragma unroll
        for (int nt = 0; nt < 8; nt++) {
            const int n_lo = n0 + wn * 64 + nt * 8 + 2 * cq;
            const int s = n_lo >> 5, c = n_lo & 31;
            const int i = i0 + wm * 32 + mt * 16 + r;
            const size_t base0 = ((size_t)s * I_DIM + i) * HC + h * 32 + c;
            const size_t base1 = base0 + (size_t)8 * HC;
            float2 g0 = *(const float2*)(g_gate + base0);
            float2 g1 = *(const float2*)(g_gate + base1);
            *(float2*)(g_wt + base0) = make_float2(f2tf32(g0.x * acc[mt][nt][0]),
                                                   f2tf32(g0.y * acc[mt][nt][1]));
            *(float2*)(g_wt + base1) = make_float2(f2tf32(g1.x * acc[mt][nt][2]),
                                                   f2tf32(g1.y * acc[mt][nt][3]));
        }
    }
}

// ---------------------------------------------------------------------------
// K5: out = g_wt @ W_out  ([196608 x 256] @ [256 x 64]) via mma.sync tf32.
// Block 128 rows; warps 4m x 2n, warp tile 32x32. B (Wout^T) resident 64KB,
// A streamed in 32-float chunks, double-buffered.
// SMEM: Wsh 64KB @0 ; A 2x16KB @64KB. Total 96KB.
// ---------------------------------------------------------------------------
__global__ __launch_bounds__(256) void k5_out(float* __restrict__ outp)
{
    extern __shared__ char smc[];
    const uint32_t sb = smem_u32(smc);
    char* Wsh = smc;

    const int t    = threadIdx.x;
    const int lane = t & 31;
    const int warp = t >> 5;
    const int wm   = warp >> 1;
    const int wn   = warp & 1;
    const int r    = lane >> 2;
    const int cq   = lane & 3;
    const int rb   = blockIdx.x * 128;

    {   // B: Wout^T pre-swizzled, straight copy (4096 float4)
        const float4* src = (const float4*)g_wot;
        float4* dst = (float4*)Wsh;
        #pragma unroll
        for (int u = 0; u < 16; u++) dst[u * 256 + t] = src[u * 256 + t];
    }

    const float* Agl = g_wt + (size_t)rb * HC;

    auto LOAD = [&](int kc, int buf) {
        const uint32_t Ab = sb + 65536 + buf * 16384;
        const int k0 = kc * 32;
        #pragma unroll
        for (int u = 0; u < 4; u++) {
            int lin = u * 256 + t;
            int row = lin >> 3, q = lin & 7;
            cp_async16(Ab + swz128(row * 128 + q * 16),
                       Agl + (size_t)row * HC + k0 + q * 4);
        }
        cp_commit();
    };

    float acc[2][4][4];
    #pragma unroll
    for (int mt = 0; mt < 2; mt++)
        #pragma unroll
        for (int nt = 0; nt < 4; nt++)
            #pragma unroll
            for (int e = 0; e < 4; e++) acc[mt][nt][e] = 0.f;

    LOAD(0, 0);

    #pragma unroll 1
    for (int kc = 0; kc < 8; kc++) {
        const int buf = kc & 1;
        if (kc < 7) { LOAD(kc + 1, buf ^ 1); cp_wait1(); }
        else        { cp_wait0(); }
        __syncthreads();

        const char* Ab = smc + 65536 + buf * 16384;

        #pragma unroll
        for (int ks = 0; ks < 4; ks++) {
            const int klo = ks * 8 + cq, khi = klo + 4;       // within chunk
            const int gklo = kc * 32 + klo, gkhi = kc * 32 + khi;  // global k
            uint32_t a[2][4];
            #pragma unroll
            for (int mt = 0; mt < 2; mt++) {
                const int row0 = wm * 32 + mt * 16 + r;
                a[mt][0] = *(const uint32_t*)(Ab + bo(row0,     klo, 128));
                a[mt][1] = *(const uint32_t*)(Ab + bo(row0 + 8, klo, 128));
                a[mt][2] = *(const uint32_t*)(Ab + bo(row0,     khi, 128));
                a[mt][3] = *(const uint32_t*)(Ab + bo(row0 + 8, khi, 128));
            }
            uint32_t b[4][2];
            #pragma unroll
            for (int nt = 0; nt < 4; nt++) {
                const int n = wn * 32 + nt * 8 + r;
                b[nt][0] = *(const uint32_t*)(Wsh + bo(n, gklo, 1024));
                b[nt][1] = *(const uint32_t*)(Wsh + bo(n, gkhi, 1024));
            }
            #pragma unroll
            for (int mt = 0; mt < 2; mt++)
                #pragma unroll
                for (int nt = 0; nt < 4; nt++)
                    mma_tf32(acc[mt][nt], a[mt], b[nt]);
        }
        __syncthreads();
    }

    #pragma unroll
    for (int mt = 0; mt < 2; mt++) {
        #pragma unroll
        for (int nt = 0; nt < 4; nt++) {
            const int n   = wn * 32 + nt * 8 + 2 * cq;
            const int row = rb + wm * 32 + mt * 16 + r;
            *(float2*)(outp + (size_t)row * CM + n) =
                make_float2(acc[mt][nt][0], acc[mt][nt][1]);
            *(float2*)(outp + (size_t)(row + 8) * CM + n) =
                make_float2(acc[mt][nt][2], acc[mt][nt][3]);
        }
    }
}

// ---------------------------------------------------------------------------
extern "C" void kernel_launch(void* const* d_in, const int* in_sizes, int n_in,
                              void* d_out, int out_size)
{
    (void)in_sizes; (void)n_in; (void)out_size;
    const float* msa  = (const float*)d_in[0];
    const float* pair = (const float*)d_in[1];
    const float* lmg  = (const float*)d_in[2];
    const float* lmb  = (const float*)d_in[3];
    const float* lpg  = (const float*)d_in[4];
    const float* lpb  = (const float*)d_in[5];
    const float* Wv   = (const float*)d_in[6];
    const float* Wb   = (const float*)d_in[7];
    const float* Wg   = (const float*)d_in[8];
    const float* Wo   = (const float*)d_in[9];
    float* outp = (float*)d_out;

    cudaFuncSetAttribute(k1_v_gate, cudaFuncAttributeMaxDynamicSharedMemorySize, 98304);
    cudaFuncSetAttribute(k4_gemm,   cudaFuncAttributeMaxDynamicSharedMemorySize, 65536);
    cudaFuncSetAttribute(k5_out,    cudaFuncAttributeMaxDynamicSharedMemorySize, 98304);

    k0_prep<<<1, 256>>>(Wv, Wg, Wo);
    k1_v_gate<<<(S_DIM * I_DIM) / 128, 256, 98304>>>(msa, lmg, lmb);
    k2_bias<<<I_DIM * I_DIM, 128>>>(pair, lpg, lpb, Wb);
    k3_softmax<<<I_DIM * H_DIM, 128>>>();
    k4_gemm<<<dim3(3, 128, 8), 256, 65536>>>();
    k5_out<<<(S_DIM * I_DIM) / 128, 256, 98304>>>(outp);
}

// round 6
// speedup vs baseline: 3.0907x; 1.1520x over previous
#include <cuda_runtime.h>
#include <cstdint>

// MSAPairWeightedAverage — round 6: occupancy fix (launch_bounds 2 blocks),
// coalesced g_v writes via SMEM staging, warp-per-row k2.
// S=512, I=384, C_MSA=64, C_Z=128, H=8, C=32 (H*C=256)

#define S_DIM 512
#define I_DIM 384
#define CM    64
#define CZ    128
#define H_DIM 8
#define HC    256
#define LN_EPS 1e-5f

__device__ float g_v[(size_t)H_DIM * S_DIM * 32 * I_DIM];   // [h][n=s*32+c][j]  (K-major B)
__device__ float g_gate[(size_t)S_DIM * I_DIM * HC];        // [s][i][hc]
__device__ float g_wt[(size_t)S_DIM * I_DIM * HC];          // [s][i][hc] gate*weights (tf32)
__device__ float g_bias[(size_t)I_DIM * H_DIM * I_DIM];     // [i][h][j]
__device__ float g_w[(size_t)H_DIM * I_DIM * I_DIM];        // [h][i][j]  (K-major A)
__device__ float g_wvt[256 * 64];                           // Wv^T  swizzled tf32
__device__ float g_wgt[256 * 64];                           // Wg^T  swizzled tf32
__device__ float g_wot[64 * 256];                           // Wout^T swizzled tf32

// ---------------------------------------------------------------------------
__device__ __forceinline__ float f2tf32(float x) {
    uint32_t r;
    asm("cvt.rna.tf32.f32 %0, %1;" : "=r"(r) : "f"(x));
    return __uint_as_float(r);
}
__device__ __forceinline__ void cp_async16(uint32_t dst, const void* src) {
    asm volatile("cp.async.cg.shared.global [%0], [%1], 16;" :: "r"(dst), "l"(src));
}
__device__ __forceinline__ void cp_commit() { asm volatile("cp.async.commit_group;" ::: "memory"); }
__device__ __forceinline__ void cp_wait1()  { asm volatile("cp.async.wait_group 1;"  ::: "memory"); }
__device__ __forceinline__ void cp_wait0()  { asm volatile("cp.async.wait_group 0;"  ::: "memory"); }
__device__ __forceinline__ uint32_t smem_u32(const void* p) {
    uint32_t a;
    asm("{ .reg .u64 t; cvta.to.shared.u64 t, %1; cvt.u32.u64 %0, t; }" : "=r"(a) : "l"(p));
    return a;
}
__device__ __forceinline__ uint32_t swz128(uint32_t off) { return off ^ ((off >> 3) & 0x70); }
__device__ __forceinline__ uint32_t bo(int row, int k, int rowBytes) {
    return (uint32_t)(row * rowBytes + ((((k >> 2) ^ (row & 7)) << 4) | ((k & 3) << 2)));
}
__device__ __forceinline__ void mma_tf32(float* d, const uint32_t* a, const uint32_t* b) {
    asm volatile(
        "mma.sync.aligned.m16n8k8.row.col.f32.tf32.tf32.f32 "
        "{%0,%1,%2,%3}, {%4,%5,%6,%7}, {%8,%9}, {%0,%1,%2,%3};"
        : "+f"(d[0]), "+f"(d[1]), "+f"(d[2]), "+f"(d[3])
        : "r"(a[0]), "r"(a[1]), "r"(a[2]), "r"(a[3]), "r"(b[0]), "r"(b[1]));
}

// ---------------------------------------------------------------------------
// K0: prep transposed, tf32-rounded, pre-swizzled weights.
// ---------------------------------------------------------------------------
__global__ __launch_bounds__(256) void k0_prep(
    const float* __restrict__ Wv, const float* __restrict__ Wg,
    const float* __restrict__ Wo)
{
    const int t = threadIdx.x;
    #pragma unroll 4
    for (int k = 0; k < 64; k++) {
        uint32_t idx = bo(t, k, 256) >> 2;
        g_wvt[idx] = f2tf32(Wv[k * 256 + t]);
        g_wgt[idx] = f2tf32(Wg[k * 256 + t]);
    }
    const int n = t & 63, kb = (t >> 6) * 64;
    #pragma unroll 4
    for (int kk = 0; kk < 64; kk++) {
        const int k = kb + kk;
        g_wot[bo(n, k, 1024) >> 2] = f2tf32(Wo[k * 64 + n]);
    }
}

// ---------------------------------------------------------------------------
// K1: LN(msa) -> Ash (tf32); v = A @ Wv (staged, coalesced to g_v), gate = sigmoid(A @ Wg).
// SMEM: Ash 32KB @0 ; Wsh 64KB @32KB ; Dsh [128][132] 67584B @96KB. Total 165888.
// ---------------------------------------------------------------------------
__global__ __launch_bounds__(256) void k1_v_gate(
    const float* __restrict__ msa,
    const float* __restrict__ ln_g, const float* __restrict__ ln_b)
{
    extern __shared__ char smc[];
    char*  Ash = smc;
    char*  Wsh = smc + 32768;
    float* Dsh = (float*)(smc + 98304);   // [128][132]

    const int t    = threadIdx.x;
    const int lane = t & 31;
    const int warp = t >> 5;
    const int wm   = warp >> 1;
    const int wn   = warp & 1;
    const int r    = lane >> 2;
    const int cq   = lane & 3;

    const int rb    = blockIdx.x * 128;
    const int s_idx = rb / I_DIM;
    const int j0    = rb - s_idx * I_DIM;

    const float lg0 = ln_g[lane], lg1 = ln_g[lane + 32];
    const float lb0 = ln_b[lane], lb1 = ln_b[lane + 32];
    #pragma unroll 4
    for (int rr = 0; rr < 16; rr++) {
        const int row = warp * 16 + rr;
        const float* x = msa + (size_t)(rb + row) * CM;
        float x0 = x[lane], x1 = x[lane + 32];
        float s = x0 + x1, s2 = x0 * x0 + x1 * x1;
        #pragma unroll
        for (int o = 16; o; o >>= 1) {
            s  += __shfl_xor_sync(0xffffffffu, s,  o);
            s2 += __shfl_xor_sync(0xffffffffu, s2, o);
        }
        float mu  = s * (1.f / 64.f);
        float var = s2 * (1.f / 64.f) - mu * mu;
        float rs  = rsqrtf(var + LN_EPS);
        *(float*)(Ash + bo(row, lane,      256)) = f2tf32((x0 - mu) * rs * lg0 + lb0);
        *(float*)(Ash + bo(row, lane + 32, 256)) = f2tf32((x1 - mu) * rs * lg1 + lb1);
    }

    for (int p = 0; p < 2; p++) {
        __syncthreads();
        {
            const float4* src = (const float4*)(p ? g_wgt : g_wvt);
            float4* dst = (float4*)Wsh;
            #pragma unroll
            for (int u = 0; u < 16; u++) dst[u * 256 + t] = src[u * 256 + t];
        }
        __syncthreads();

        for (int nh = 0; nh < 2; nh++) {
            float acc[2][8][4];
            #pragma unroll
            for (int mt = 0; mt < 2; mt++)
                #pragma unroll
                for (int nt = 0; nt < 8; nt++)
                    #pragma unroll
                    for (int e = 0; e < 4; e++) acc[mt][nt][e] = 0.f;

            #pragma unroll
            for (int ks = 0; ks < 8; ks++) {
                const int klo = ks * 8 + cq, khi = klo + 4;
                uint32_t a[2][4];
                #pragma unroll
                for (int mt = 0; mt < 2; mt++) {
                    const int row0 = wm * 32 + mt * 16 + r;
                    a[mt][0] = *(const uint32_t*)(Ash + bo(row0,     klo, 256));
                    a[mt][1] = *(const uint32_t*)(Ash + bo(row0 + 8, klo, 256));
                    a[mt][2] = *(const uint32_t*)(Ash + bo(row0,     khi, 256));
                    a[mt][3] = *(const uint32_t*)(Ash + bo(row0 + 8, khi, 256));
                }
                uint32_t b[8][2];
                #pragma unroll
                for (int nt = 0; nt < 8; nt++) {
                    const int n = nh * 128 + wn * 64 + nt * 8 + r;
                    b[nt][0] = *(const uint32_t*)(Wsh + bo(n, klo, 256));
                    b[nt][1] = *(const uint32_t*)(Wsh + bo(n, khi, 256));
                }
                #pragma unroll
                for (int mt = 0; mt < 2; mt++)
                    #pragma unroll
                    for (int nt = 0; nt < 8; nt++)
                        mma_tf32(acc[mt][nt], a[mt], b[nt]);
            }

            if (p == 0) {
                // stage D -> Dsh[nc_local][row], then coalesced copy to g_v
                #pragma unroll
                for (int mt = 0; mt < 2; mt++) {
                    #pragma unroll
                    for (int nt = 0; nt < 8; nt++) {
                        const int ncl = wn * 64 + nt * 8 + 2 * cq;
                        const int row = wm * 32 + mt * 16 + r;
                        Dsh[ncl * 132 + row]           = f2tf32(acc[mt][nt][0]);
                        Dsh[(ncl + 1) * 132 + row]     = f2tf32(acc[mt][nt][1]);
                        Dsh[ncl * 132 + row + 8]       = f2tf32(acc[mt][nt][2]);
                        Dsh[(ncl + 1) * 132 + row + 8] = f2tf32(acc[mt][nt][3]);
                    }
                }
                __syncthreads();
                // copy: 128 nc rows x 32 float4 (j), fully coalesced along j
                #pragma unroll
                for (int u = 0; u < 16; u++) {
                    const int idx = u * 256 + t;       // 0..4095
                    const int q   = idx & 31;          // float4 within row
                    const int ncl = idx >> 5;          // 0..127
                    const int nc  = nh * 128 + ncl;
                    const int h   = nc >> 5, c = nc & 31;
                    const float* srow = Dsh + ncl * 132 + q * 4;
                    float4 val = make_float4(srow[0], srow[1], srow[2], srow[3]);
                    float* drow = g_v + ((size_t)h * 16384 + s_idx * 32 + c) * I_DIM + j0;
                    ((float4*)drow)[q] = val;
                }
                __syncthreads();
            } else {
                #pragma unroll
                for (int mt = 0; mt < 2; mt++) {
                    #pragma unroll
                    for (int nt = 0; nt < 8; nt++) {
                        const int nc  = nh * 128 + wn * 64 + nt * 8 + 2 * cq;
                        const int row = wm * 32 + mt * 16 + r;
                        float* base = g_gate + (size_t)(rb + row) * HC + nc;
                        *(float2*)base = make_float2(
                            1.f / (1.f + __expf(-acc[mt][nt][0])),
                            1.f / (1.f + __expf(-acc[mt][nt][1])));
                        *(float2*)(base + (size_t)8 * HC) = make_float2(
                            1.f / (1.f + __expf(-acc[mt][nt][2])),
                            1.f / (1.f + __expf(-acc[mt][nt][3])));
                    }
                }
            }
        }
    }
}

// ---------------------------------------------------------------------------
// K2: bias[i][h][j] = LN(pair[i][j]) @ W_bias.  Warp-per-row, 8 rows/block.
// ---------------------------------------------------------------------------
__global__ __launch_bounds__(256) void k2_bias(
    const float* __restrict__ pair,
    const float* __restrict__ gz, const float* __restrict__ bz,
    const float* __restrict__ Wb)
{
    __shared__ float Wbs[8 * 128];   // [h][col]
    __shared__ float gzs[128], bzs[128];

    const int t = threadIdx.x;
    const int lane = t & 31, warp = t >> 5;
    const int row = blockIdx.x * 8 + warp;
    const int i = row / I_DIM, j = row - i * I_DIM;

    #pragma unroll
    for (int u = 0; u < 4; u++) {
        const int idx = u * 256 + t;       // 0..1023
        const int h = idx >> 7, col = idx & 127;
        Wbs[h * 128 + col] = Wb[col * 8 + h];
    }
    if (t < 128) { gzs[t] = gz[t]; bzs[t] = bz[t]; }
    __syncthreads();

    const float* x = pair + (size_t)row * CZ;
    float xv[4];
    #pragma unroll
    for (int c = 0; c < 4; c++) xv[c] = x[lane + 32 * c];

    float s = 0.f, s2 = 0.f;
    #pragma unroll
    for (int c = 0; c < 4; c++) { s += xv[c]; s2 += xv[c] * xv[c]; }
    #pragma unroll
    for (int o = 16; o; o >>= 1) {
        s  += __shfl_xor_sync(0xffffffffu, s,  o);
        s2 += __shfl_xor_sync(0xffffffffu, s2, o);
    }
    const float mu  = s * (1.f / 128.f);
    const float var = s2 * (1.f / 128.f) - mu * mu;
    const float rs  = rsqrtf(var + LN_EPS);

    float p[8];
    #pragma unroll
    for (int h = 0; h < 8; h++) p[h] = 0.f;
    #pragma unroll
    for (int c = 0; c < 4; c++) {
        const int col = lane + 32 * c;
        const float xn = (xv[c] - mu) * rs * gzs[col] + bzs[col];
        #pragma unroll
        for (int h = 0; h < 8; h++) p[h] += xn * Wbs[h * 128 + col];
    }
    #pragma unroll
    for (int h = 0; h < 8; h++) {
        #pragma unroll
        for (int o = 16; o; o >>= 1) p[h] += __shfl_xor_sync(0xffffffffu, p[h], o);
    }
    if (lane < 8)
        g_bias[((size_t)i * H_DIM + lane) * I_DIM + j] = p[lane];
}

// ---------------------------------------------------------------------------
// K3: w[h][i][j] = softmax_j(bias[i][h][j])  (tf32-rounded stores)
// ---------------------------------------------------------------------------
__global__ __launch_bounds__(128) void k3_softmax()
{
    __shared__ float red[4];
    __shared__ float bval;

    const int t = threadIdx.x;
    const int lane = t & 31, warp = t >> 5;
    const int b = blockIdx.x;
    const int i = b >> 3, h = b & 7;

    const float* src = g_bias + ((size_t)i * H_DIM + h) * I_DIM;
    float x0 = src[t], x1 = src[t + 128], x2 = src[t + 256];

    float m = fmaxf(x0, fmaxf(x1, x2));
    #pragma unroll
    for (int o = 16; o; o >>= 1) m = fmaxf(m, __shfl_xor_sync(0xffffffffu, m, o));
    if (lane == 0) red[warp] = m;
    __syncthreads();
    if (t == 0) bval = fmaxf(fmaxf(red[0], red[1]), fmaxf(red[2], red[3]));
    __syncthreads();
    const float mx = bval;

    float e0 = __expf(x0 - mx), e1 = __expf(x1 - mx), e2 = __expf(x2 - mx);
    float s = e0 + e1 + e2;
    #pragma unroll
    for (int o = 16; o; o >>= 1) s += __shfl_xor_sync(0xffffffffu, s, o);
    __syncthreads();
    if (lane == 0) red[warp] = s;
    __syncthreads();
    if (t == 0) bval = red[0] + red[1] + red[2] + red[3];
    __syncthreads();
    const float inv = 1.f / bval;

    float* dst = g_w + ((size_t)h * I_DIM + i) * I_DIM;
    dst[t]       = f2tf32(e0 * inv);
    dst[t + 128] = f2tf32(e1 * inv);
    dst[t + 256] = f2tf32(e2 * inv);
}

// ---------------------------------------------------------------------------
// K4: mma.sync tf32 GEMM per head:  D[i, n] = sum_j w[h][i][j] * v[h][n][j]
// Grid (3, 128, 8); 2 blocks/SM forced. Epilogue: gate multiply -> g_wt (tf32).
// ---------------------------------------------------------------------------
__global__ __launch_bounds__(256, 2) void k4_gemm()
{
    extern __shared__ char smc[];
    const uint32_t sb = smem_u32(smc);

    const int t    = threadIdx.x;
    const int lane = t & 31;
    const int warp = t >> 5;
    const int wm   = warp >> 1;
    const int wn   = warp & 1;
    const int r    = lane >> 2;
    const int cq   = lane & 3;

    const int i0 = blockIdx.x * 128;
    const int n0 = blockIdx.y * 128;
    const int h  = blockIdx.z;

    const float* Ag = g_w + ((size_t)h * I_DIM + i0) * I_DIM;
    const float* Bg = g_v + ((size_t)h * 16384 + n0) * I_DIM;

    float acc[2][8][4];
    #pragma unroll
    for (int mt = 0; mt < 2; mt++)
        #pragma unroll
        for (int nt = 0; nt < 8; nt++)
            #pragma unroll
            for (int e = 0; e < 4; e++) acc[mt][nt][e] = 0.f;

    auto LOAD = [&](int kc, int buf) {
        const uint32_t Ab = sb + buf * 16384;
        const uint32_t Bb = sb + 32768 + buf * 16384;
        const int k0 = kc * 32;
        #pragma unroll
        for (int u = 0; u < 4; u++) {
            int lin = u * 256 + t;
            int row = lin >> 3, q = lin & 7;
            cp_async16(Ab + swz128(row * 128 + q * 16),
                       Ag + (size_t)row * I_DIM + k0 + q * 4);
        }
        #pragma unroll
        for (int u = 0; u < 4; u++) {
            int lin = u * 256 + t;
            int row = lin >> 3, q = lin & 7;
            cp_async16(Bb + swz128(row * 128 + q * 16),
                       Bg + (size_t)row * I_DIM + k0 + q * 4);
        }
        cp_commit();
    };

    LOAD(0, 0);

    #pragma unroll 1
    for (int kc = 0; kc < 12; kc++) {
        const int buf = kc & 1;
        if (kc < 11) { LOAD(kc + 1, buf ^ 1); cp_wait1(); }
        else         { cp_wait0(); }
        __syncthreads();

        const char* Ab = smc + buf * 16384;
        const char* Bb = smc + 32768 + buf * 16384;

        #pragma unroll
        for (int ks = 0; ks < 4; ks++) {
            const int klo = ks * 8 + cq, khi = klo + 4;
            uint32_t a[2][4];
            #pragma unroll
            for (int mt = 0; mt < 2; mt++) {
                const int row0 = wm * 32 + mt * 16 + r;
                a[mt][0] = *(const uint32_t*)(Ab + bo(row0,     klo, 128));
                a[mt][1] = *(const uint32_t*)(Ab + bo(row0 + 8, klo, 128));
                a[mt][2] = *(const uint32_t*)(Ab + bo(row0,     khi, 128));
                a[mt][3] = *(const uint32_t*)(Ab + bo(row0 + 8, khi, 128));
            }
            uint32_t b[8][2];
            #pragma unroll
            for (int nt = 0; nt < 8; nt++) {
                const int rown = wn * 64 + nt * 8 + r;
                b[nt][0] = *(const uint32_t*)(Bb + bo(rown, klo, 128));
                b[nt][1] = *(const uint32_t*)(Bb + bo(rown, khi, 128));
            }
            #pragma unroll
            for (int mt = 0; mt < 2; mt++)
                #pragma unroll
                for (int nt = 0; nt < 8; nt++)
                    mma_tf32(acc[mt][nt], a[mt], b[nt]);
        }
        __syncthreads();
    }

    #pragma unroll
    for (int mt = 0; mt < 2; mt++) {
        #pragma unroll
        for (int nt = 0; nt < 8; nt++) {
            const int n_lo = n0 + wn * 64 + nt * 8 + 2 * cq;
            const int s = n_lo >> 5, c = n_lo & 31;
            const int i = i0 + wm * 32 + mt * 16 + r;
            const size_t base0 = ((size_t)s * I_DIM + i) * HC + h * 32 + c;
            const size_t base1 = base0 + (size_t)8 * HC;
            float2 g0 = *(const float2*)(g_gate + base0);
            float2 g1 = *(const float2*)(g_gate + base1);
            *(float2*)(g_wt + base0) = make_float2(f2tf32(g0.x * acc[mt][nt][0]),
                                                   f2tf32(g0.y * acc[mt][nt][1]));
            *(float2*)(g_wt + base1) = make_float2(f2tf32(g1.x * acc[mt][nt][2]),
                                                   f2tf32(g1.y * acc[mt][nt][3]));
        }
    }
}

// ---------------------------------------------------------------------------
// K5: out = g_wt @ W_out  via mma.sync tf32.  2 blocks/SM forced.
// ---------------------------------------------------------------------------
__global__ __launch_bounds__(256, 2) void k5_out(float* __restrict__ outp)
{
    extern __shared__ char smc[];
    const uint32_t sb = smem_u32(smc);
    char* Wsh = smc;

    const int t    = threadIdx.x;
    const int lane = t & 31;
    const int warp = t >> 5;
    const int wm   = warp >> 1;
    const int wn   = warp & 1;
    const int r    = lane >> 2;
    const int cq   = lane & 3;
    const int rb   = blockIdx.x * 128;

    {
        const float4* src = (const float4*)g_wot;
        float4* dst = (float4*)Wsh;
        #pragma unroll
        for (int u = 0; u < 16; u++) dst[u * 256 + t] = src[u * 256 + t];
    }

    const float* Agl = g_wt + (size_t)rb * HC;

    auto LOAD = [&](int kc, int buf) {
        const uint32_t Ab = sb + 65536 + buf * 16384;
        const int k0 = kc * 32;
        #pragma unroll
        for (int u = 0; u < 4; u++) {
            int lin = u * 256 + t;
            int row = lin >> 3, q = lin & 7;
            cp_async16(Ab + swz128(row * 128 + q * 16),
                       Agl + (size_t)row * HC + k0 + q * 4);
        }
        cp_commit();
    };

    float acc[2][4][4];
    #pragma unroll
    for (int mt = 0; mt < 2; mt++)
        #pragma unroll
        for (int nt = 0; nt < 4; nt++)
            #pragma unroll
            for (int e = 0; e < 4; e++) acc[mt][nt][e] = 0.f;

    LOAD(0, 0);

    #pragma unroll 1
    for (int kc = 0; kc < 8; kc++) {
        const int buf = kc & 1;
        if (kc < 7) { LOAD(kc + 1, buf ^ 1); cp_wait1(); }
        else        { cp_wait0(); }
        __syncthreads();

        const char* Ab = smc + 65536 + buf * 16384;

        #pragma unroll
        for (int ks = 0; ks < 4; ks++) {
            const int klo = ks * 8 + cq, khi = klo + 4;
            const int gklo = kc * 32 + klo, gkhi = kc * 32 + khi;
            uint32_t a[2][4];
            #pragma unroll
            for (int mt = 0; mt < 2; mt++) {
                const int row0 = wm * 32 + mt * 16 + r;
                a[mt][0] = *(const uint32_t*)(Ab + bo(row0,     klo, 128));
                a[mt][1] = *(const uint32_t*)(Ab + bo(row0 + 8, klo, 128));
                a[mt][2] = *(const uint32_t*)(Ab + bo(row0,     khi, 128));
                a[mt][3] = *(const uint32_t*)(Ab + bo(row0 + 8, khi, 128));
            }
            uint32_t b[4][2];
            #pragma unroll
            for (int nt = 0; nt < 4; nt++) {
                const int n = wn * 32 + nt * 8 + r;
                b[nt][0] = *(const uint32_t*)(Wsh + bo(n, gklo, 1024));
                b[nt][1] = *(const uint32_t*)(Wsh + bo(n, gkhi, 1024));
            }
            #pragma unroll
            for (int mt = 0; mt < 2; mt++)
                #pragma unroll
                for (int nt = 0; nt < 4; nt++)
                    mma_tf32(acc[mt][nt], a[mt], b[nt]);
        }
        __syncthreads();
    }

    #pragma unroll
    for (int mt = 0; mt < 2; mt++) {
        #pragma unroll
        for (int nt = 0; nt < 4; nt++) {
            const int n   = wn * 32 + nt * 8 + 2 * cq;
            const int row = rb + wm * 32 + mt * 16 + r;
            *(float2*)(outp + (size_t)row * CM + n) =
                make_float2(acc[mt][nt][0], acc[mt][nt][1]);
            *(float2*)(outp + (size_t)(row + 8) * CM + n) =
                make_float2(acc[mt][nt][2], acc[mt][nt][3]);
        }
    }
}

// ---------------------------------------------------------------------------
extern "C" void kernel_launch(void* const* d_in, const int* in_sizes, int n_in,
                              void* d_out, int out_size)
{
    (void)in_sizes; (void)n_in; (void)out_size;
    const float* msa  = (const float*)d_in[0];
    const float* pair = (const float*)d_in[1];
    const float* lmg  = (const float*)d_in[2];
    const float* lmb  = (const float*)d_in[3];
    const float* lpg  = (const float*)d_in[4];
    const float* lpb  = (const float*)d_in[5];
    const float* Wv   = (const float*)d_in[6];
    const float* Wb   = (const float*)d_in[7];
    const float* Wg   = (const float*)d_in[8];
    const float* Wo   = (const float*)d_in[9];
    float* outp = (float*)d_out;

    cudaFuncSetAttribute(k1_v_gate, cudaFuncAttributeMaxDynamicSharedMemorySize, 165888);
    cudaFuncSetAttribute(k4_gemm,   cudaFuncAttributeMaxDynamicSharedMemorySize, 65536);
    cudaFuncSetAttribute(k5_out,    cudaFuncAttributeMaxDynamicSharedMemorySize, 98304);

    k0_prep<<<1, 256>>>(Wv, Wg, Wo);
    k1_v_gate<<<(S_DIM * I_DIM) / 128, 256, 165888>>>(msa, lmg, lmb);
    k2_bias<<<(I_DIM * I_DIM) / 8, 256>>>(pair, lpg, lpb, Wb);
    k3_softmax<<<I_DIM * H_DIM, 128>>>();
    k4_gemm<<<dim3(3, 128, 8), 256, 65536>>>();
    k5_out<<<(S_DIM * I_DIM) / 128, 256, 98304>>>(outp);
}

// round 8
// speedup vs baseline: 3.3913x; 1.0973x over previous
#include <cuda_runtime.h>
#include <cstdint>

// MSAPairWeightedAverage — round 7: k1 2-CTA occupancy (chunked Dsh),
// 3-stage cp.async pipelines in k4/k5.
// S=512, I=384, C_MSA=64, C_Z=128, H=8, C=32 (H*C=256)

#define S_DIM 512
#define I_DIM 384
#define CM    64
#define CZ    128
#define H_DIM 8
#define HC    256
#define LN_EPS 1e-5f

__device__ float g_v[(size_t)H_DIM * S_DIM * 32 * I_DIM];   // [h][n=s*32+c][j]  (K-major B)
__device__ float g_gate[(size_t)S_DIM * I_DIM * HC];        // [s][i][hc]
__device__ float g_wt[(size_t)S_DIM * I_DIM * HC];          // [s][i][hc] gate*weights (tf32)
__device__ float g_bias[(size_t)I_DIM * H_DIM * I_DIM];     // [i][h][j]
__device__ float g_w[(size_t)H_DIM * I_DIM * I_DIM];        // [h][i][j]  (K-major A)
__device__ float g_wvt[256 * 64];                           // Wv^T  swizzled tf32
__device__ float g_wgt[256 * 64];                           // Wg^T  swizzled tf32
__device__ float g_wot[64 * 256];                           // Wout^T swizzled tf32

// ---------------------------------------------------------------------------
__device__ __forceinline__ float f2tf32(float x) {
    uint32_t r;
    asm("cvt.rna.tf32.f32 %0, %1;" : "=r"(r) : "f"(x));
    return __uint_as_float(r);
}
__device__ __forceinline__ void cp_async16(uint32_t dst, const void* src) {
    asm volatile("cp.async.cg.shared.global [%0], [%1], 16;" :: "r"(dst), "l"(src));
}
__device__ __forceinline__ void cp_commit() { asm volatile("cp.async.commit_group;" ::: "memory"); }
__device__ __forceinline__ void cp_wait2()  { asm volatile("cp.async.wait_group 2;"  ::: "memory"); }
__device__ __forceinline__ void cp_wait1()  { asm volatile("cp.async.wait_group 1;"  ::: "memory"); }
__device__ __forceinline__ void cp_wait0()  { asm volatile("cp.async.wait_group 0;"  ::: "memory"); }
__device__ __forceinline__ uint32_t smem_u32(const void* p) {
    uint32_t a;
    asm("{ .reg .u64 t; cvta.to.shared.u64 t, %1; cvt.u32.u64 %0, t; }" : "=r"(a) : "l"(p));
    return a;
}
__device__ __forceinline__ uint32_t swz128(uint32_t off) { return off ^ ((off >> 3) & 0x70); }
__device__ __forceinline__ uint32_t bo(int row, int k, int rowBytes) {
    return (uint32_t)(row * rowBytes + ((((k >> 2) ^ (row & 7)) << 4) | ((k & 3) << 2)));
}
__device__ __forceinline__ void mma_tf32(float* d, const uint32_t* a, const uint32_t* b) {
    asm volatile(
        "mma.sync.aligned.m16n8k8.row.col.f32.tf32.tf32.f32 "
        "{%0,%1,%2,%3}, {%4,%5,%6,%7}, {%8,%9}, {%0,%1,%2,%3};"
        : "+f"(d[0]), "+f"(d[1]), "+f"(d[2]), "+f"(d[3])
        : "r"(a[0]), "r"(a[1]), "r"(a[2]), "r"(a[3]), "r"(b[0]), "r"(b[1]));
}

// ---------------------------------------------------------------------------
// K0: prep transposed, tf32-rounded, pre-swizzled weights.
// ---------------------------------------------------------------------------
__global__ __launch_bounds__(256) void k0_prep(
    const float* __restrict__ Wv, const float* __restrict__ Wg,
    const float* __restrict__ Wo)
{
    const int t = threadIdx.x;
    #pragma unroll 4
    for (int k = 0; k < 64; k++) {
        uint32_t idx = bo(t, k, 256) >> 2;
        g_wvt[idx] = f2tf32(Wv[k * 256 + t]);
        g_wgt[idx] = f2tf32(Wg[k * 256 + t]);
    }
    const int n = t & 63, kb = (t >> 6) * 64;
    #pragma unroll 4
    for (int kk = 0; kk < 64; kk++) {
        const int k = kb + kk;
        g_wot[bo(n, k, 1024) >> 2] = f2tf32(Wo[k * 64 + n]);
    }
}

// ---------------------------------------------------------------------------
// K1: LN(msa) -> Ash (tf32); v = A @ Wv (chunk-staged, coalesced), gate = sigmoid(A @ Wg).
// SMEM: Ash 32KB @0 ; Wsh 64KB @32768 ; Dsh [32][132] 16896B @98304. Total 115200.
// 2 CTAs/SM.
// ---------------------------------------------------------------------------
__global__ __launch_bounds__(256, 2) void k1_v_gate(
    const float* __restrict__ msa,
    const float* __restrict__ ln_g, const float* __restrict__ ln_b)
{
    extern __shared__ char smc[];
    char*  Ash = smc;
    char*  Wsh = smc + 32768;
    float* Dsh = (float*)(smc + 98304);   // [32][132]

    const int t    = threadIdx.x;
    const int lane = t & 31;
    const int warp = t >> 5;
    const int wm   = warp >> 1;
    const int wn   = warp & 1;
    const int r    = lane >> 2;
    const int cq   = lane & 3;

    const int rb    = blockIdx.x * 128;
    const int s_idx = rb / I_DIM;
    const int j0    = rb - s_idx * I_DIM;

    const float lg0 = ln_g[lane], lg1 = ln_g[lane + 32];
    const float lb0 = ln_b[lane], lb1 = ln_b[lane + 32];
    #pragma unroll 4
    for (int rr = 0; rr < 16; rr++) {
        const int row = warp * 16 + rr;
        const float* x = msa + (size_t)(rb + row) * CM;
        float x0 = x[lane], x1 = x[lane + 32];
        float s = x0 + x1, s2 = x0 * x0 + x1 * x1;
        #pragma unroll
        for (int o = 16; o; o >>= 1) {
            s  += __shfl_xor_sync(0xffffffffu, s,  o);
            s2 += __shfl_xor_sync(0xffffffffu, s2, o);
        }
        float mu  = s * (1.f / 64.f);
        float var = s2 * (1.f / 64.f) - mu * mu;
        float rs  = rsqrtf(var + LN_EPS);
        *(float*)(Ash + bo(row, lane,      256)) = f2tf32((x0 - mu) * rs * lg0 + lb0);
        *(float*)(Ash + bo(row, lane + 32, 256)) = f2tf32((x1 - mu) * rs * lg1 + lb1);
    }

    for (int p = 0; p < 2; p++) {
        __syncthreads();
        {
            const float4* src = (const float4*)(p ? g_wgt : g_wvt);
            float4* dst = (float4*)Wsh;
            #pragma unroll
            for (int u = 0; u < 16; u++) dst[u * 256 + t] = src[u * 256 + t];
        }
        __syncthreads();

        for (int nh = 0; nh < 2; nh++) {
            float acc[2][8][4];
            #pragma unroll
            for (int mt = 0; mt < 2; mt++)
                #pragma unroll
                for (int nt = 0; nt < 8; nt++)
                    #pragma unroll
                    for (int e = 0; e < 4; e++) acc[mt][nt][e] = 0.f;

            #pragma unroll
            for (int ks = 0; ks < 8; ks++) {
                const int klo = ks * 8 + cq, khi = klo + 4;
                uint32_t a[2][4];
                #pragma unroll
                for (int mt = 0; mt < 2; mt++) {
                    const int row0 = wm * 32 + mt * 16 + r;
                    a[mt][0] = *(const uint32_t*)(Ash + bo(row0,     klo, 256));
                    a[mt][1] = *(const uint32_t*)(Ash + bo(row0 + 8, klo, 256));
                    a[mt][2] = *(const uint32_t*)(Ash + bo(row0,     khi, 256));
                    a[mt][3] = *(const uint32_t*)(Ash + bo(row0 + 8, khi, 256));
                }
                uint32_t b[8][2];
                #pragma unroll
                for (int nt = 0; nt < 8; nt++) {
                    const int n = nh * 128 + wn * 64 + nt * 8 + r;
                    b[nt][0] = *(const uint32_t*)(Wsh + bo(n, klo, 256));
                    b[nt][1] = *(const uint32_t*)(Wsh + bo(n, khi, 256));
                }
                #pragma unroll
                for (int mt = 0; mt < 2; mt++)
                    #pragma unroll
                    for (int nt = 0; nt < 8; nt++)
                        mma_tf32(acc[mt][nt], a[mt], b[nt]);
            }

            if (p == 0) {
                // 4 chunks of 32 nc each: stage -> coalesced g_v write
                #pragma unroll
                for (int cb = 0; cb < 4; cb++) {
                    if (wn == (cb >> 1)) {
                        const int ntlo = (cb & 1) * 4;
                        #pragma unroll
                        for (int mt = 0; mt < 2; mt++) {
                            #pragma unroll
                            for (int nt2 = 0; nt2 < 4; nt2++) {
                                const int nt  = ntlo + nt2;
                                const int ncl = nt2 * 8 + 2 * cq;   // 0..30
                                const int row = wm * 32 + mt * 16 + r;
                                Dsh[ncl * 132 + row]           = f2tf32(acc[mt][nt][0]);
                                Dsh[(ncl + 1) * 132 + row]     = f2tf32(acc[mt][nt][1]);
                                Dsh[ncl * 132 + row + 8]       = f2tf32(acc[mt][nt][2]);
                                Dsh[(ncl + 1) * 132 + row + 8] = f2tf32(acc[mt][nt][3]);
                            }
                        }
                    }
                    __syncthreads();
                    #pragma unroll
                    for (int u = 0; u < 4; u++) {
                        const int idx  = u * 256 + t;     // 0..1023
                        const int q    = idx & 31;        // = lane
                        const int rloc = idx >> 5;        // 0..31
                        const int nc   = nh * 128 + cb * 32 + rloc;
                        const int h    = nc >> 5, c = nc & 31;
                        float4 val = *(const float4*)(Dsh + rloc * 132 + q * 4);
                        float* drow =
                            g_v + ((size_t)h * 16384 + s_idx * 32 + c) * I_DIM + j0;
                        ((float4*)drow)[q] = val;
                    }
                    __syncthreads();
                }
            } else {
                #pragma unroll
                for (int mt = 0; mt < 2; mt++) {
                    #pragma unroll
                    for (int nt = 0; nt < 8; nt++) {
                        const int nc  = nh * 128 + wn * 64 + nt * 8 + 2 * cq;
                        const int row = wm * 32 + mt * 16 + r;
                        float* base = g_gate + (size_t)(rb + row) * HC + nc;
                        *(float2*)base = make_float2(
                            1.f / (1.f + __expf(-acc[mt][nt][0])),
                            1.f / (1.f + __expf(-acc[mt][nt][1])));
                        *(float2*)(base + (size_t)8 * HC) = make_float2(
                            1.f / (1.f + __expf(-acc[mt][nt][2])),
                            1.f / (1.f + __expf(-acc[mt][nt][3])));
                    }
                }
            }
        }
    }
}

// ---------------------------------------------------------------------------
// K2: bias[i][h][j] = LN(pair[i][j]) @ W_bias.  Warp-per-row, 8 rows/block.
// ---------------------------------------------------------------------------
__global__ __launch_bounds__(256) void k2_bias(
    const float* __restrict__ pair,
    const float* __restrict__ gz, const float* __restrict__ bz,
    const float* __restrict__ Wb)
{
    __shared__ float Wbs[8 * 128];
    __shared__ float gzs[128], bzs[128];

    const int t = threadIdx.x;
    const int lane = t & 31, warp = t >> 5;
    const int row = blockIdx.x * 8 + warp;
    const int i = row / I_DIM, j = row - i * I_DIM;

    #pragma unroll
    for (int u = 0; u < 4; u++) {
        const int idx = u * 256 + t;
        const int h = idx >> 7, col = idx & 127;
        Wbs[h * 128 + col] = Wb[col * 8 + h];
    }
    if (t < 128) { gzs[t] = gz[t]; bzs[t] = bz[t]; }
    __syncthreads();

    const float* x = pair + (size_t)row * CZ;
    float xv[4];
    #pragma unroll
    for (int c = 0; c < 4; c++) xv[c] = x[lane + 32 * c];

    float s = 0.f, s2 = 0.f;
    #pragma unroll
    for (int c = 0; c < 4; c++) { s += xv[c]; s2 += xv[c] * xv[c]; }
    #pragma unroll
    for (int o = 16; o; o >>= 1) {
        s  += __shfl_xor_sync(0xffffffffu, s,  o);
        s2 += __shfl_xor_sync(0xffffffffu, s2, o);
    }
    const float mu  = s * (1.f / 128.f);
    const float var = s2 * (1.f / 128.f) - mu * mu;
    const float rs  = rsqrtf(var + LN_EPS);

    float p[8];
    #pragma unroll
    for (int h = 0; h < 8; h++) p[h] = 0.f;
    #pragma unroll
    for (int c = 0; c < 4; c++) {
        const int col = lane + 32 * c;
        const float xn = (xv[c] - mu) * rs * gzs[col] + bzs[col];
        #pragma unroll
        for (int h = 0; h < 8; h++) p[h] += xn * Wbs[h * 128 + col];
    }
    #pragma unroll
    for (int h = 0; h < 8; h++) {
        #pragma unroll
        for (int o = 16; o; o >>= 1) p[h] += __shfl_xor_sync(0xffffffffu, p[h], o);
    }
    if (lane < 8)
        g_bias[((size_t)i * H_DIM + lane) * I_DIM + j] = p[lane];
}

// ---------------------------------------------------------------------------
// K3: w[h][i][j] = softmax_j(bias[i][h][j])  (tf32-rounded stores)
// ---------------------------------------------------------------------------
__global__ __launch_bounds__(128) void k3_softmax()
{
    __shared__ float red[4];
    __shared__ float bval;

    const int t = threadIdx.x;
    const int lane = t & 31, warp = t >> 5;
    const int b = blockIdx.x;
    const int i = b >> 3, h = b & 7;

    const float* src = g_bias + ((size_t)i * H_DIM + h) * I_DIM;
    float x0 = src[t], x1 = src[t + 128], x2 = src[t + 256];

    float m = fmaxf(x0, fmaxf(x1, x2));
    #pragma unroll
    for (int o = 16; o; o >>= 1) m = fmaxf(m, __shfl_xor_sync(0xffffffffu, m, o));
    if (lane == 0) red[warp] = m;
    __syncthreads();
    if (t == 0) bval = fmaxf(fmaxf(red[0], red[1]), fmaxf(red[2], red[3]));
    __syncthreads();
    const float mx = bval;

    float e0 = __expf(x0 - mx), e1 = __expf(x1 - mx), e2 = __expf(x2 - mx);
    float s = e0 + e1 + e2;
    #pragma unroll
    for (int o = 16; o; o >>= 1) s += __shfl_xor_sync(0xffffffffu, s, o);
    __syncthreads();
    if (lane == 0) red[warp] = s;
    __syncthreads();
    if (t == 0) bval = red[0] + red[1] + red[2] + red[3];
    __syncthreads();
    const float inv = 1.f / bval;

    float* dst = g_w + ((size_t)h * I_DIM + i) * I_DIM;
    dst[t]       = f2tf32(e0 * inv);
    dst[t + 128] = f2tf32(e1 * inv);
    dst[t + 256] = f2tf32(e2 * inv);
}

// ---------------------------------------------------------------------------
// K4: mma.sync tf32 GEMM per head. Grid (3, 128, 8); 2 CTAs/SM; 3-stage pipeline.
// SMEM: 3 stages x (A 16KB + B 16KB) = 96KB.
// ---------------------------------------------------------------------------
__global__ __launch_bounds__(256, 2) void k4_gemm()
{
    extern __shared__ char smc[];
    const uint32_t sb = smem_u32(smc);

    const int t    = threadIdx.x;
    const int lane = t & 31;
    const int warp = t >> 5;
    const int wm   = warp >> 1;
    const int wn   = warp & 1;
    const int r    = lane >> 2;
    const int cq   = lane & 3;

    const int i0 = blockIdx.x * 128;
    const int n0 = blockIdx.y * 128;
    const int h  = blockIdx.z;

    const float* Ag = g_w + ((size_t)h * I_DIM + i0) * I_DIM;
    const float* Bg = g_v + ((size_t)h * 16384 + n0) * I_DIM;

    float acc[2][8][4];
    #pragma unroll
    for (int mt = 0; mt < 2; mt++)
        #pragma unroll
        for (int nt = 0; nt < 8; nt++)
            #pragma unroll
            for (int e = 0; e < 4; e++) acc[mt][nt][e] = 0.f;

    auto LOAD = [&](int kc, int buf) {
        const uint32_t Ab = sb + buf * 32768;
        const uint32_t Bb = Ab + 16384;
        const int k0 = kc * 32;
        #pragma unroll
        for (int u = 0; u < 4; u++) {
            int lin = u * 256 + t;
            int row = lin >> 3, q = lin & 7;
            cp_async16(Ab + swz128(row * 128 + q * 16),
                       Ag + (size_t)row * I_DIM + k0 + q * 4);
        }
        #pragma unroll
        for (int u = 0; u < 4; u++) {
            int lin = u * 256 + t;
            int row = lin >> 3, q = lin & 7;
            cp_async16(Bb + swz128(row * 128 + q * 16),
                       Bg + (size_t)row * I_DIM + k0 + q * 4);
        }
        cp_commit();
    };

    LOAD(0, 0);
    LOAD(1, 1);

    #pragma unroll 1
    for (int kc = 0; kc < 12; kc++) {
        const int buf = kc % 3;
        if (kc + 2 < 12) LOAD(kc + 2, (kc + 2) % 3);
        if (kc < 10)      cp_wait2();
        else if (kc == 10) cp_wait1();
        else               cp_wait0();
        __syncthreads();

        const char* Ab = smc + buf * 32768;
        const char* Bb = Ab + 16384;

        #pragma unroll
        for (int ks = 0; ks < 4; ks++) {
            const int klo = ks * 8 + cq, khi = klo + 4;
            uint32_t a[2][4];
            #pragma unroll
            for (int mt = 0; mt < 2; mt++) {
                const int row0 = wm * 32 + mt * 16 + r;
                a[mt][0] = *(const uint32_t*)(Ab + bo(row0,     klo, 128));
                a[mt][1] = *(const uint32_t*)(Ab + bo(row0 + 8, klo, 128));
                a[mt][2] = *(const uint32_t*)(Ab + bo(row0,     khi, 128));
                a[mt][3] = *(const uint32_t*)(Ab + bo(row0 + 8, khi, 128));
            }
            uint32_t b[8][2];
            #pragma unroll
            for (int nt = 0; nt < 8; nt++) {
                const int rown = wn * 64 + nt * 8 + r;
                b[nt][0] = *(const uint32_t*)(Bb + bo(rown, klo, 128));
                b[nt][1] = *(const uint32_t*)(Bb + bo(rown, khi, 128));
            }
            #pragma unroll
            for (int mt = 0; mt < 2; mt++)
                #pragma unroll
                for (int nt = 0; nt < 8; nt++)
                    mma_tf32(acc[mt][nt], a[mt], b[nt]);
        }
        __syncthreads();
    }

    #pragma unroll
    for (int mt = 0; mt < 2; mt++) {
        #pragma unroll
        for (int nt = 0; nt < 8; nt++) {
            const int n_lo = n0 + wn * 64 + nt * 8 + 2 * cq;
            const int s = n_lo >> 5, c = n_lo & 31;
            const int i = i0 + wm * 32 + mt * 16 + r;
            const size_t base0 = ((size_t)s * I_DIM + i) * HC + h * 32 + c;
            const size_t base1 = base0 + (size_t)8 * HC;
            float2 g0 = *(const float2*)(g_gate + base0);
            float2 g1 = *(const float2*)(g_gate + base1);
            *(float2*)(g_wt + base0) = make_float2(f2tf32(g0.x * acc[mt][nt][0]),
                                                   f2tf32(g0.y * acc[mt][nt][1]));
            *(float2*)(g_wt + base1) = make_float2(f2tf32(g1.x * acc[mt][nt][2]),
                                                   f2tf32(g1.y * acc[mt][nt][3]));
        }
    }
}

// ---------------------------------------------------------------------------
// K5: out = g_wt @ W_out via mma.sync tf32. 2 CTAs/SM; 3-stage A pipeline.
// SMEM: Wsh 64KB @0 ; 3 stages x 16KB @65536. Total 114688.
// ---------------------------------------------------------------------------
__global__ __launch_bounds__(256, 2) void k5_out(float* __restrict__ outp)
{
    extern __shared__ char smc[];
    const uint32_t sb = smem_u32(smc);
    char* Wsh = smc;

    const int t    = threadIdx.x;
    const int lane = t & 31;
    const int warp = t >> 5;
    const int wm   = warp >> 1;
    const int wn   = warp & 1;
    const int r    = lane >> 2;
    const int cq   = lane & 3;
    const int rb   = blockIdx.x * 128;

    {
        const float4* src = (const float4*)g_wot;
        float4* dst = (float4*)Wsh;
        #pragma unroll
        for (int u = 0; u < 16; u++) dst[u * 256 + t] = src[u * 256 + t];
    }

    const float* Agl = g_wt + (size_t)rb * HC;

    auto LOAD = [&](int kc, int buf) {
        const uint32_t Ab = sb + 65536 + buf * 16384;
        const int k0 = kc * 32;
        #pragma unroll
        for (int u = 0; u < 4; u++) {
            int lin = u * 256 + t;
            int row = lin >> 3, q = lin & 7;
            cp_async16(Ab + swz128(row * 128 + q * 16),
                       Agl + (size_t)row * HC + k0 + q * 4);
        }
        cp_commit();
    };

    float acc[2][4][4];
    #pragma unroll
    for (int mt = 0; mt < 2; mt++)
        #pragma unroll
        for (int nt = 0; nt < 4; nt++)
            #pragma unroll
            for (int e = 0; e < 4; e++) acc[mt][nt][e] = 0.f;

    LOAD(0, 0);
    LOAD(1, 1);

    #pragma unroll 1
    for (int kc = 0; kc < 8; kc++) {
        const int buf = kc % 3;
        if (kc + 2 < 8) LOAD(kc + 2, (kc + 2) % 3);
        if (kc < 6)      cp_wait2();
        else if (kc == 6) cp_wait1();
        else              cp_wait0();
        __syncthreads();

        const char* Ab = smc + 65536 + buf * 16384;

        #pragma unroll
        for (int ks = 0; ks < 4; ks++) {
            const int klo = ks * 8 + cq, khi = klo + 4;
            const int gklo = kc * 32 + klo, gkhi = kc * 32 + khi;
            uint32_t a[2][4];
            #pragma unroll
            for (int mt = 0; mt < 2; mt++) {
                const int row0 = wm * 32 + mt * 16 + r;
                a[mt][0] = *(const uint32_t*)(Ab + bo(row0,     klo, 128));
                a[mt][1] = *(const uint32_t*)(Ab + bo(row0 + 8, klo, 128));
                a[mt][2] = *(const uint32_t*)(Ab + bo(row0,     khi, 128));
                a[mt][3] = *(const uint32_t*)(Ab + bo(row0 + 8, khi, 128));
            }
            uint32_t b[4][2];
            #pragma unroll
            for (int nt = 0; nt < 4; nt++) {
                const int n = wn * 32 + nt * 8 + r;
                b[nt][0] = *(const uint32_t*)(Wsh + bo(n, gklo, 1024));
                b[nt][1] = *(const uint32_t*)(Wsh + bo(n, gkhi, 1024));
            }
            #pragma unroll
            for (int mt = 0; mt < 2; mt++)
                #pragma unroll
                for (int nt = 0; nt < 4; nt++)
                    mma_tf32(acc[mt][nt], a[mt], b[nt]);
        }
        __syncthreads();
    }

    #pragma unroll
    for (int mt = 0; mt < 2; mt++) {
        #pragma unroll
        for (int nt = 0; nt < 4; nt++) {
            const int n   = wn * 32 + nt * 8 + 2 * cq;
            const int row = rb + wm * 32 + mt * 16 + r;
            *(float2*)(outp + (size_t)row * CM + n) =
                make_float2(acc[mt][nt][0], acc[mt][nt][1]);
            *(float2*)(outp + (size_t)(row + 8) * CM + n) =
                make_float2(acc[mt][nt][2], acc[mt][nt][3]);
        }
    }
}

// ---------------------------------------------------------------------------
extern "C" void kernel_launch(void* const* d_in, const int* in_sizes, int n_in,
                              void* d_out, int out_size)
{
    (void)in_sizes; (void)n_in; (void)out_size;
    const float* msa  = (const float*)d_in[0];
    const float* pair = (const float*)d_in[1];
    const float* lmg  = (const float*)d_in[2];
    const float* lmb  = (const float*)d_in[3];
    const float* lpg  = (const float*)d_in[4];
    const float* lpb  = (const float*)d_in[5];
    const float* Wv   = (const float*)d_in[6];
    const float* Wb   = (const float*)d_in[7];
    const float* Wg   = (const float*)d_in[8];
    const float* Wo   = (const float*)d_in[9];
    float* outp = (float*)d_out;

    cudaFuncSetAttribute(k1_v_gate, cudaFuncAttributeMaxDynamicSharedMemorySize, 115200);
    cudaFuncSetAttribute(k4_gemm,   cudaFuncAttributeMaxDynamicSharedMemorySize, 98304);
    cudaFuncSetAttribute(k5_out,    cudaFuncAttributeMaxDynamicSharedMemorySize, 114688);

    k0_prep<<<1, 256>>>(Wv, Wg, Wo);
    k1_v_gate<<<(S_DIM * I_DIM) / 128, 256, 115200>>>(msa, lmg, lmb);
    k2_bias<<<(I_DIM * I_DIM) / 8, 256>>>(pair, lpg, lpb, Wb);
    k3_softmax<<<I_DIM * H_DIM, 128>>>();
    k4_gemm<<<dim3(3, 128, 8), 256, 98304>>>();
    k5_out<<<(S_DIM * I_DIM) / 128, 256, 114688>>>(outp);
}

// round 9
// speedup vs baseline: 3.4506x; 1.0175x over previous
#include <cuda_runtime.h>
#include <cstdint>

// MSAPairWeightedAverage — round 9: u16 gate (−200MB DRAM), single-barrier
// 3-stage pipelines in k4/k5.
// S=512, I=384, C_MSA=64, C_Z=128, H=8, C=32 (H*C=256)

#define S_DIM 512
#define I_DIM 384
#define CM    64
#define CZ    128
#define H_DIM 8
#define HC    256
#define LN_EPS 1e-5f

__device__ float g_v[(size_t)H_DIM * S_DIM * 32 * I_DIM];     // [h][n=s*32+c][j]
__device__ unsigned short g_gate16[(size_t)S_DIM * I_DIM * HC]; // [s][i][hc] u16 fixed
__device__ float g_wt[(size_t)S_DIM * I_DIM * HC];            // [s][i][hc] gate*weights (tf32)
__device__ float g_bias[(size_t)I_DIM * H_DIM * I_DIM];       // [i][h][j]
__device__ float g_w[(size_t)H_DIM * I_DIM * I_DIM];          // [h][i][j]
__device__ float g_wvt[256 * 64];                             // Wv^T swizzled tf32
__device__ float g_wgt[256 * 64];                             // Wg^T swizzled tf32
__device__ float g_wot[64 * 256];                             // Wout^T swizzled tf32

#define GATE_SCALE   65535.0f
#define GATE_INV     (1.0f / 65535.0f)

// ---------------------------------------------------------------------------
__device__ __forceinline__ float f2tf32(float x) {
    uint32_t r;
    asm("cvt.rna.tf32.f32 %0, %1;" : "=r"(r) : "f"(x));
    return __uint_as_float(r);
}
__device__ __forceinline__ void cp_async16(uint32_t dst, const void* src) {
    asm volatile("cp.async.cg.shared.global [%0], [%1], 16;" :: "r"(dst), "l"(src));
}
__device__ __forceinline__ void cp_commit() { asm volatile("cp.async.commit_group;" ::: "memory"); }
__device__ __forceinline__ void cp_wait1()  { asm volatile("cp.async.wait_group 1;"  ::: "memory"); }
__device__ __forceinline__ void cp_wait0()  { asm volatile("cp.async.wait_group 0;"  ::: "memory"); }
__device__ __forceinline__ uint32_t smem_u32(const void* p) {
    uint32_t a;
    asm("{ .reg .u64 t; cvta.to.shared.u64 t, %1; cvt.u32.u64 %0, t; }" : "=r"(a) : "l"(p));
    return a;
}
__device__ __forceinline__ uint32_t swz128(uint32_t off) { return off ^ ((off >> 3) & 0x70); }
__device__ __forceinline__ uint32_t bo(int row, int k, int rowBytes) {
    return (uint32_t)(row * rowBytes + ((((k >> 2) ^ (row & 7)) << 4) | ((k & 3) << 2)));
}
__device__ __forceinline__ void mma_tf32(float* d, const uint32_t* a, const uint32_t* b) {
    asm volatile(
        "mma.sync.aligned.m16n8k8.row.col.f32.tf32.tf32.f32 "
        "{%0,%1,%2,%3}, {%4,%5,%6,%7}, {%8,%9}, {%0,%1,%2,%3};"
        : "+f"(d[0]), "+f"(d[1]), "+f"(d[2]), "+f"(d[3])
        : "r"(a[0]), "r"(a[1]), "r"(a[2]), "r"(a[3]), "r"(b[0]), "r"(b[1]));
}
__device__ __forceinline__ uint32_t pack_gate(float a, float b) {
    uint32_t lo = __float2uint_rn(a * GATE_SCALE);
    uint32_t hi = __float2uint_rn(b * GATE_SCALE);
    return lo | (hi << 16);
}

// ---------------------------------------------------------------------------
// K0: prep transposed, tf32-rounded, pre-swizzled weights.
// ---------------------------------------------------------------------------
__global__ __launch_bounds__(256) void k0_prep(
    const float* __restrict__ Wv, const float* __restrict__ Wg,
    const float* __restrict__ Wo)
{
    const int t = threadIdx.x;
    #pragma unroll 4
    for (int k = 0; k < 64; k++) {
        uint32_t idx = bo(t, k, 256) >> 2;
        g_wvt[idx] = f2tf32(Wv[k * 256 + t]);
        g_wgt[idx] = f2tf32(Wg[k * 256 + t]);
    }
    const int n = t & 63, kb = (t >> 6) * 64;
    #pragma unroll 4
    for (int kk = 0; kk < 64; kk++) {
        const int k = kb + kk;
        g_wot[bo(n, k, 1024) >> 2] = f2tf32(Wo[k * 64 + n]);
    }
}

// ---------------------------------------------------------------------------
// K1: LN(msa) -> Ash (tf32); v = A @ Wv (chunk-staged, coalesced),
//     gate = sigmoid(A @ Wg) -> u16 packed.
// SMEM: Ash 32KB @0 ; Wsh 64KB @32768 ; Dsh [32][132] @98304. Total 115200. 2 CTAs/SM.
// ---------------------------------------------------------------------------
__global__ __launch_bounds__(256, 2) void k1_v_gate(
    const float* __restrict__ msa,
    const float* __restrict__ ln_g, const float* __restrict__ ln_b)
{
    extern __shared__ char smc[];
    char*  Ash = smc;
    char*  Wsh = smc + 32768;
    float* Dsh = (float*)(smc + 98304);

    const int t    = threadIdx.x;
    const int lane = t & 31;
    const int warp = t >> 5;
    const int wm   = warp >> 1;
    const int wn   = warp & 1;
    const int r    = lane >> 2;
    const int cq   = lane & 3;

    const int rb    = blockIdx.x * 128;
    const int s_idx = rb / I_DIM;
    const int j0    = rb - s_idx * I_DIM;

    const float lg0 = ln_g[lane], lg1 = ln_g[lane + 32];
    const float lb0 = ln_b[lane], lb1 = ln_b[lane + 32];
    #pragma unroll 4
    for (int rr = 0; rr < 16; rr++) {
        const int row = warp * 16 + rr;
        const float* x = msa + (size_t)(rb + row) * CM;
        float x0 = x[lane], x1 = x[lane + 32];
        float s = x0 + x1, s2 = x0 * x0 + x1 * x1;
        #pragma unroll
        for (int o = 16; o; o >>= 1) {
            s  += __shfl_xor_sync(0xffffffffu, s,  o);
            s2 += __shfl_xor_sync(0xffffffffu, s2, o);
        }
        float mu  = s * (1.f / 64.f);
        float var = s2 * (1.f / 64.f) - mu * mu;
        float rs  = rsqrtf(var + LN_EPS);
        *(float*)(Ash + bo(row, lane,      256)) = f2tf32((x0 - mu) * rs * lg0 + lb0);
        *(float*)(Ash + bo(row, lane + 32, 256)) = f2tf32((x1 - mu) * rs * lg1 + lb1);
    }

    for (int p = 0; p < 2; p++) {
        __syncthreads();
        {
            const float4* src = (const float4*)(p ? g_wgt : g_wvt);
            float4* dst = (float4*)Wsh;
            #pragma unroll
            for (int u = 0; u < 16; u++) dst[u * 256 + t] = src[u * 256 + t];
        }
        __syncthreads();

        for (int nh = 0; nh < 2; nh++) {
            float acc[2][8][4];
            #pragma unroll
            for (int mt = 0; mt < 2; mt++)
                #pragma unroll
                for (int nt = 0; nt < 8; nt++)
                    #pragma unroll
                    for (int e = 0; e < 4; e++) acc[mt][nt][e] = 0.f;

            #pragma unroll
            for (int ks = 0; ks < 8; ks++) {
                const int klo = ks * 8 + cq, khi = klo + 4;
                uint32_t a[2][4];
                #pragma unroll
                for (int mt = 0; mt < 2; mt++) {
                    const int row0 = wm * 32 + mt * 16 + r;
                    a[mt][0] = *(const uint32_t*)(Ash + bo(row0,     klo, 256));
                    a[mt][1] = *(const uint32_t*)(Ash + bo(row0 + 8, klo, 256));
                    a[mt][2] = *(const uint32_t*)(Ash + bo(row0,     khi, 256));
                    a[mt][3] = *(const uint32_t*)(Ash + bo(row0 + 8, khi, 256));
                }
                uint32_t b[8][2];
                #pragma unroll
                for (int nt = 0; nt < 8; nt++) {
                    const int n = nh * 128 + wn * 64 + nt * 8 + r;
                    b[nt][0] = *(const uint32_t*)(Wsh + bo(n, klo, 256));
                    b[nt][1] = *(const uint32_t*)(Wsh + bo(n, khi, 256));
                }
                #pragma unroll
                for (int mt = 0; mt < 2; mt++)
                    #pragma unroll
                    for (int nt = 0; nt < 8; nt++)
                        mma_tf32(acc[mt][nt], a[mt], b[nt]);
            }

            if (p == 0) {
                #pragma unroll
                for (int cb = 0; cb < 4; cb++) {
                    if (wn == (cb >> 1)) {
                        const int ntlo = (cb & 1) * 4;
                        #pragma unroll
                        for (int mt = 0; mt < 2; mt++) {
                            #pragma unroll
                            for (int nt2 = 0; nt2 < 4; nt2++) {
                                const int nt  = ntlo + nt2;
                                const int ncl = nt2 * 8 + 2 * cq;
                                const int row = wm * 32 + mt * 16 + r;
                                Dsh[ncl * 132 + row]           = f2tf32(acc[mt][nt][0]);
                                Dsh[(ncl + 1) * 132 + row]     = f2tf32(acc[mt][nt][1]);
                                Dsh[ncl * 132 + row + 8]       = f2tf32(acc[mt][nt][2]);
                                Dsh[(ncl + 1) * 132 + row + 8] = f2tf32(acc[mt][nt][3]);
                            }
                        }
                    }
                    __syncthreads();
                    #pragma unroll
                    for (int u = 0; u < 4; u++) {
                        const int idx  = u * 256 + t;
                        const int q    = idx & 31;
                        const int rloc = idx >> 5;
                        const int nc   = nh * 128 + cb * 32 + rloc;
                        const int h    = nc >> 5, c = nc & 31;
                        float4 val = *(const float4*)(Dsh + rloc * 132 + q * 4);
                        float* drow =
                            g_v + ((size_t)h * 16384 + s_idx * 32 + c) * I_DIM + j0;
                        ((float4*)drow)[q] = val;
                    }
                    __syncthreads();
                }
            } else {
                #pragma unroll
                for (int mt = 0; mt < 2; mt++) {
                    #pragma unroll
                    for (int nt = 0; nt < 8; nt++) {
                        const int nc  = nh * 128 + wn * 64 + nt * 8 + 2 * cq;  // even
                        const int row = wm * 32 + mt * 16 + r;
                        const size_t base = (size_t)(rb + row) * HC + nc;
                        const float s0 = 1.f / (1.f + __expf(-acc[mt][nt][0]));
                        const float s1 = 1.f / (1.f + __expf(-acc[mt][nt][1]));
                        const float s2 = 1.f / (1.f + __expf(-acc[mt][nt][2]));
                        const float s3 = 1.f / (1.f + __expf(-acc[mt][nt][3]));
                        *(uint32_t*)(g_gate16 + base)                   = pack_gate(s0, s1);
                        *(uint32_t*)(g_gate16 + base + (size_t)8 * HC)  = pack_gate(s2, s3);
                    }
                }
            }
        }
    }
}

// ---------------------------------------------------------------------------
// K2: bias[i][h][j] = LN(pair[i][j]) @ W_bias.  Warp-per-row, 8 rows/block.
// ---------------------------------------------------------------------------
__global__ __launch_bounds__(256) void k2_bias(
    const float* __restrict__ pair,
    const float* __restrict__ gz, const float* __restrict__ bz,
    const float* __restrict__ Wb)
{
    __shared__ float Wbs[8 * 128];
    __shared__ float gzs[128], bzs[128];

    const int t = threadIdx.x;
    const int lane = t & 31, warp = t >> 5;
    const int row = blockIdx.x * 8 + warp;
    const int i = row / I_DIM, j = row - i * I_DIM;

    #pragma unroll
    for (int u = 0; u < 4; u++) {
        const int idx = u * 256 + t;
        const int h = idx >> 7, col = idx & 127;
        Wbs[h * 128 + col] = Wb[col * 8 + h];
    }
    if (t < 128) { gzs[t] = gz[t]; bzs[t] = bz[t]; }
    __syncthreads();

    const float* x = pair + (size_t)row * CZ;
    float xv[4];
    #pragma unroll
    for (int c = 0; c < 4; c++) xv[c] = x[lane + 32 * c];

    float s = 0.f, s2 = 0.f;
    #pragma unroll
    for (int c = 0; c < 4; c++) { s += xv[c]; s2 += xv[c] * xv[c]; }
    #pragma unroll
    for (int o = 16; o; o >>= 1) {
        s  += __shfl_xor_sync(0xffffffffu, s,  o);
        s2 += __shfl_xor_sync(0xffffffffu, s2, o);
    }
    const float mu  = s * (1.f / 128.f);
    const float var = s2 * (1.f / 128.f) - mu * mu;
    const float rs  = rsqrtf(var + LN_EPS);

    float p[8];
    #pragma unroll
    for (int h = 0; h < 8; h++) p[h] = 0.f;
    #pragma unroll
    for (int c = 0; c < 4; c++) {
        const int col = lane + 32 * c;
        const float xn = (xv[c] - mu) * rs * gzs[col] + bzs[col];
        #pragma unroll
        for (int h = 0; h < 8; h++) p[h] += xn * Wbs[h * 128 + col];
    }
    #pragma unroll
    for (int h = 0; h < 8; h++) {
        #pragma unroll
        for (int o = 16; o; o >>= 1) p[h] += __shfl_xor_sync(0xffffffffu, p[h], o);
    }
    if (lane < 8)
        g_bias[((size_t)i * H_DIM + lane) * I_DIM + j] = p[lane];
}

// ---------------------------------------------------------------------------
// K3: w[h][i][j] = softmax_j(bias[i][h][j])  (tf32-rounded stores)
// ---------------------------------------------------------------------------
__global__ __launch_bounds__(128) void k3_softmax()
{
    __shared__ float red[4];
    __shared__ float bval;

    const int t = threadIdx.x;
    const int lane = t & 31, warp = t >> 5;
    const int b = blockIdx.x;
    const int i = b >> 3, h = b & 7;

    const float* src = g_bias + ((size_t)i * H_DIM + h) * I_DIM;
    float x0 = src[t], x1 = src[t + 128], x2 = src[t + 256];

    float m = fmaxf(x0, fmaxf(x1, x2));
    #pragma unroll
    for (int o = 16; o; o >>= 1) m = fmaxf(m, __shfl_xor_sync(0xffffffffu, m, o));
    if (lane == 0) red[warp] = m;
    __syncthreads();
    if (t == 0) bval = fmaxf(fmaxf(red[0], red[1]), fmaxf(red[2], red[3]));
    __syncthreads();
    const float mx = bval;

    float e0 = __expf(x0 - mx), e1 = __expf(x1 - mx), e2 = __expf(x2 - mx);
    float s = e0 + e1 + e2;
    #pragma unroll
    for (int o = 16; o; o >>= 1) s += __shfl_xor_sync(0xffffffffu, s, o);
    __syncthreads();
    if (lane == 0) red[warp] = s;
    __syncthreads();
    if (t == 0) bval = red[0] + red[1] + red[2] + red[3];
    __syncthreads();
    const float inv = 1.f / bval;

    float* dst = g_w + ((size_t)h * I_DIM + i) * I_DIM;
    dst[t]       = f2tf32(e0 * inv);
    dst[t + 128] = f2tf32(e1 * inv);
    dst[t + 256] = f2tf32(e2 * inv);
}

// ---------------------------------------------------------------------------
// K4: mma.sync tf32 GEMM per head. Grid (3, 128, 8); 2 CTAs/SM; 3-stage,
// single barrier per chunk (load issued after barrier, overlapping MMA).
// ---------------------------------------------------------------------------
__global__ __launch_bounds__(256, 2) void k4_gemm()
{
    extern __shared__ char smc[];
    const uint32_t sb = smem_u32(smc);

    const int t    = threadIdx.x;
    const int lane = t & 31;
    const int warp = t >> 5;
    const int wm   = warp >> 1;
    const int wn   = warp & 1;
    const int r    = lane >> 2;
    const int cq   = lane & 3;

    const int i0 = blockIdx.x * 128;
    const int n0 = blockIdx.y * 128;
    const int h  = blockIdx.z;

    const float* Ag = g_w + ((size_t)h * I_DIM + i0) * I_DIM;
    const float* Bg = g_v + ((size_t)h * 16384 + n0) * I_DIM;

    float acc[2][8][4];
    #pragma unroll
    for (int mt = 0; mt < 2; mt++)
        #pragma unroll
        for (int nt = 0; nt < 8; nt++)
            #pragma unroll
            for (int e = 0; e < 4; e++) acc[mt][nt][e] = 0.f;

    auto LOAD = [&](int kc, int buf) {
        const uint32_t Ab = sb + buf * 32768;
        const uint32_t Bb = Ab + 16384;
        const int k0 = kc * 32;
        #pragma unroll
        for (int u = 0; u < 4; u++) {
            int lin = u * 256 + t;
            int row = lin >> 3, q = lin & 7;
            cp_async16(Ab + swz128(row * 128 + q * 16),
                       Ag + (size_t)row * I_DIM + k0 + q * 4);
        }
        #pragma unroll
        for (int u = 0; u < 4; u++) {
            int lin = u * 256 + t;
            int row = lin >> 3, q = lin & 7;
            cp_async16(Bb + swz128(row * 128 + q * 16),
                       Bg + (size_t)row * I_DIM + k0 + q * 4);
        }
        cp_commit();
    };

    LOAD(0, 0);
    LOAD(1, 1);

    #pragma unroll 1
    for (int kc = 0; kc < 12; kc++) {
        const int buf = kc % 3;
        if (kc < 11) cp_wait1(); else cp_wait0();
        __syncthreads();
        if (kc + 2 < 12) LOAD(kc + 2, (kc + 2) % 3);

        const char* Ab = smc + buf * 32768;
        const char* Bb = Ab + 16384;

        #pragma unroll
        for (int ks = 0; ks < 4; ks++) {
            const int klo = ks * 8 + cq, khi = klo + 4;
            uint32_t a[2][4];
            #pragma unroll
            for (int mt = 0; mt < 2; mt++) {
                const int row0 = wm * 32 + mt * 16 + r;
                a[mt][0] = *(const uint32_t*)(Ab + bo(row0,     klo, 128));
                a[mt][1] = *(const uint32_t*)(Ab + bo(row0 + 8, klo, 128));
                a[mt][2] = *(const uint32_t*)(Ab + bo(row0,     khi, 128));
                a[mt][3] = *(const uint32_t*)(Ab + bo(row0 + 8, khi, 128));
            }
            uint32_t b[8][2];
            #pragma unroll
            for (int nt = 0; nt < 8; nt++) {
                const int rown = wn * 64 + nt * 8 + r;
                b[nt][0] = *(const uint32_t*)(Bb + bo(rown, klo, 128));
                b[nt][1] = *(const uint32_t*)(Bb + bo(rown, khi, 128));
            }
            #pragma unroll
            for (int mt = 0; mt < 2; mt++)
                #pragma unroll
                for (int nt = 0; nt < 8; nt++)
                    mma_tf32(acc[mt][nt], a[mt], b[nt]);
        }
    }

    #pragma unroll
    for (int mt = 0; mt < 2; mt++) {
        #pragma unroll
        for (int nt = 0; nt < 8; nt++) {
            const int n_lo = n0 + wn * 64 + nt * 8 + 2 * cq;
            const int s = n_lo >> 5, c = n_lo & 31;
            const int i = i0 + wm * 32 + mt * 16 + r;
            const size_t base0 = ((size_t)s * I_DIM + i) * HC + h * 32 + c;
            const size_t base1 = base0 + (size_t)8 * HC;
            const uint32_t u0 = *(const uint32_t*)(g_gate16 + base0);
            const uint32_t u1 = *(const uint32_t*)(g_gate16 + base1);
            *(float2*)(g_wt + base0) = make_float2(
                f2tf32((float)(u0 & 0xffffu) * GATE_INV * acc[mt][nt][0]),
                f2tf32((float)(u0 >> 16)     * GATE_INV * acc[mt][nt][1]));
            *(float2*)(g_wt + base1) = make_float2(
                f2tf32((float)(u1 & 0xffffu) * GATE_INV * acc[mt][nt][2]),
                f2tf32((float)(u1 >> 16)     * GATE_INV * acc[mt][nt][3]));
        }
    }
}

// ---------------------------------------------------------------------------
// K5: out = g_wt @ W_out via mma.sync tf32. 2 CTAs/SM; 3-stage, single barrier.
// ---------------------------------------------------------------------------
__global__ __launch_bounds__(256, 2) void k5_out(float* __restrict__ outp)
{
    extern __shared__ char smc[];
    const uint32_t sb = smem_u32(smc);
    char* Wsh = smc;

    const int t    = threadIdx.x;
    const int lane = t & 31;
    const int warp = t >> 5;
    const int wm   = warp >> 1;
    const int wn   = warp & 1;
    const int r    = lane >> 2;
    const int cq   = lane & 3;
    const int rb   = blockIdx.x * 128;

    {
        const float4* src = (const float4*)g_wot;
        float4* dst = (float4*)Wsh;
        #pragma unroll
        for (int u = 0; u < 16; u++) dst[u * 256 + t] = src[u * 256 + t];
    }

    const float* Agl = g_wt + (size_t)rb * HC;

    auto LOAD = [&](int kc, int buf) {
        const uint32_t Ab = sb + 65536 + buf * 16384;
        const int k0 = kc * 32;
        #pragma unroll
        for (int u = 0; u < 4; u++) {
            int lin = u * 256 + t;
            int row = lin >> 3, q = lin & 7;
            cp_async16(Ab + swz128(row * 128 + q * 16),
                       Agl + (size_t)row * HC + k0 + q * 4);
        }
        cp_commit();
    };

    float acc[2][4][4];
    #pragma unroll
    for (int mt = 0; mt < 2; mt++)
        #pragma unroll
        for (int nt = 0; nt < 4; nt++)
            #pragma unroll
            for (int e = 0; e < 4; e++) acc[mt][nt][e] = 0.f;

    LOAD(0, 0);
    LOAD(1, 1);

    #pragma unroll 1
    for (int kc = 0; kc < 8; kc++) {
        const int buf = kc % 3;
        if (kc < 7) cp_wait1(); else cp_wait0();
        __syncthreads();
        if (kc + 2 < 8) LOAD(kc + 2, (kc + 2) % 3);

        const char* Ab = smc + 65536 + buf * 16384;

        #pragma unroll
        for (int ks = 0; ks < 4; ks++) {
            const int klo = ks * 8 + cq, khi = klo + 4;
            const int gklo = kc * 32 + klo, gkhi = kc * 32 + khi;
            uint32_t a[2][4];
            #pragma unroll
            for (int mt = 0; mt < 2; mt++) {
                const int row0 = wm * 32 + mt * 16 + r;
                a[mt][0] = *(const uint32_t*)(Ab + bo(row0,     klo, 128));
                a[mt][1] = *(const uint32_t*)(Ab + bo(row0 + 8, klo, 128));
                a[mt][2] = *(const uint32_t*)(Ab + bo(row0,     khi, 128));
                a[mt][3] = *(const uint32_t*)(Ab + bo(row0 + 8, khi, 128));
            }
            uint32_t b[4][2];
            #pragma unroll
            for (int nt = 0; nt < 4; nt++) {
                const int n = wn * 32 + nt * 8 + r;
                b[nt][0] = *(const uint32_t*)(Wsh + bo(n, gklo, 1024));
                b[nt][1] = *(const uint32_t*)(Wsh + bo(n, gkhi, 1024));
            }
            #pragma unroll
            for (int mt = 0; mt < 2; mt++)
                #pragma unroll
                for (int nt = 0; nt < 4; nt++)
                    mma_tf32(acc[mt][nt], a[mt], b[nt]);
        }
    }

    #pragma unroll
    for (int mt = 0; mt < 2; mt++) {
        #pragma unroll
        for (int nt = 0; nt < 4; nt++) {
            const int n   = wn * 32 + nt * 8 + 2 * cq;
            const int row = rb + wm * 32 + mt * 16 + r;
            *(float2*)(outp + (size_t)row * CM + n) =
                make_float2(acc[mt][nt][0], acc[mt][nt][1]);
            *(float2*)(outp + (size_t)(row + 8) * CM + n) =
                make_float2(acc[mt][nt][2], acc[mt][nt][3]);
        }
    }
}

// ---------------------------------------------------------------------------
extern "C" void kernel_launch(void* const* d_in, const int* in_sizes, int n_in,
                              void* d_out, int out_size)
{
    (void)in_sizes; (void)n_in; (void)out_size;
    const float* msa  = (const float*)d_in[0];
    const float* pair = (const float*)d_in[1];
    const float* lmg  = (const float*)d_in[2];
    const float* lmb  = (const float*)d_in[3];
    const float* lpg  = (const float*)d_in[4];
    const float* lpb  = (const float*)d_in[5];
    const float* Wv   = (const float*)d_in[6];
    const float* Wb   = (const float*)d_in[7];
    const float* Wg   = (const float*)d_in[8];
    const float* Wo   = (const float*)d_in[9];
    float* outp = (float*)d_out;

    cudaFuncSetAttribute(k1_v_gate, cudaFuncAttributeMaxDynamicSharedMemorySize, 115200);
    cudaFuncSetAttribute(k4_gemm,   cudaFuncAttributeMaxDynamicSharedMemorySize, 98304);
    cudaFuncSetAttribute(k5_out,    cudaFuncAttributeMaxDynamicSharedMemorySize, 114688);

    k0_prep<<<1, 256>>>(Wv, Wg, Wo);
    k1_v_gate<<<(S_DIM * I_DIM) / 128, 256, 115200>>>(msa, lmg, lmb);
    k2_bias<<<(I_DIM * I_DIM) / 8, 256>>>(pair, lpg, lpb, Wb);
    k3_softmax<<<I_DIM * H_DIM, 128>>>();
    k4_gemm<<<dim3(3, 128, 8), 256, 98304>>>();
    k5_out<<<(S_DIM * I_DIM) / 128, 256, 114688>>>(outp);
}

// round 10
// speedup vs baseline: 4.5692x; 1.3242x over previous
#include <cuda_runtime.h>
#include <cuda_fp16.h>
#include <cstdint>

// MSAPairWeightedAverage — round 10: all GEMMs on fp16 mma.sync (m16n8k16),
// fp32 accumulate. Same 10-bit mantissa as tf32, 2x tensor rate, half the bytes.
// S=512, I=384, C_MSA=64, C_Z=128, H=8, C=32 (H*C=256)

#define S_DIM 512
#define I_DIM 384
#define CM    64
#define CZ    128
#define H_DIM 8
#define HC    256
#define LN_EPS 1e-5f

__device__ __half g_v[(size_t)H_DIM * S_DIM * 32 * I_DIM];      // [h][n=s*32+c][j]
__device__ unsigned short g_gate16[(size_t)S_DIM * I_DIM * HC]; // [s][i][hc] u16 fixed
__device__ __half g_wt[(size_t)S_DIM * I_DIM * HC];             // [s][i][hc] gate*weights
__device__ float  g_bias[(size_t)I_DIM * H_DIM * I_DIM];        // [i][h][j]
__device__ __half g_w[(size_t)H_DIM * I_DIM * I_DIM];           // [h][i][j]
__device__ __half g_wvt[256 * 64];                              // Wv^T swizzled f16
__device__ __half g_wgt[256 * 64];                              // Wg^T swizzled f16
__device__ __half g_wot[64 * 256];                              // Wout^T swizzled f16

#define GATE_SCALE   65535.0f
#define GATE_INV     (1.0f / 65535.0f)

// ---------------------------------------------------------------------------
__device__ __forceinline__ void cp_async16(uint32_t dst, const void* src) {
    asm volatile("cp.async.cg.shared.global [%0], [%1], 16;" :: "r"(dst), "l"(src));
}
__device__ __forceinline__ void cp_commit() { asm volatile("cp.async.commit_group;" ::: "memory"); }
__device__ __forceinline__ void cp_wait1()  { asm volatile("cp.async.wait_group 1;"  ::: "memory"); }
__device__ __forceinline__ void cp_wait0()  { asm volatile("cp.async.wait_group 0;"  ::: "memory"); }
__device__ __forceinline__ uint32_t smem_u32(const void* p) {
    uint32_t a;
    asm("{ .reg .u64 t; cvta.to.shared.u64 t, %1; cvt.u32.u64 %0, t; }" : "=r"(a) : "l"(p));
    return a;
}
__device__ __forceinline__ uint32_t swz128(uint32_t off) { return off ^ ((off >> 3) & 0x70); }
// byte offset of half element (row, k) with 16B-granule XOR swizzle
__device__ __forceinline__ uint32_t bo16(int row, int k, int rowBytes) {
    return (uint32_t)(row * rowBytes + ((((k >> 3) ^ (row & 7)) << 4) | ((k & 7) << 1)));
}
__device__ __forceinline__ void mma_f16(float* d, const uint32_t* a, const uint32_t* b) {
    asm volatile(
        "mma.sync.aligned.m16n8k16.row.col.f32.f16.f16.f32 "
        "{%0,%1,%2,%3}, {%4,%5,%6,%7}, {%8,%9}, {%0,%1,%2,%3};"
        : "+f"(d[0]), "+f"(d[1]), "+f"(d[2]), "+f"(d[3])
        : "r"(a[0]), "r"(a[1]), "r"(a[2]), "r"(a[3]), "r"(b[0]), "r"(b[1]));
}
__device__ __forceinline__ uint32_t pack_gate(float a, float b) {
    uint32_t lo = __float2uint_rn(a * GATE_SCALE);
    uint32_t hi = __float2uint_rn(b * GATE_SCALE);
    return lo | (hi << 16);
}

// ---------------------------------------------------------------------------
// K0: prep transposed, f16, pre-swizzled weights.
// ---------------------------------------------------------------------------
__global__ __launch_bounds__(256) void k0_prep(
    const float* __restrict__ Wv, const float* __restrict__ Wg,
    const float* __restrict__ Wo)
{
    const int t = threadIdx.x;
    // Wv^T / Wg^T: [n=256][k=64] halfs, rowBytes 128. thread t = row n.
    #pragma unroll 4
    for (int k = 0; k < 64; k++) {
        uint32_t idx = bo16(t, k, 128) >> 1;
        g_wvt[idx] = __float2half_rn(Wv[k * 256 + t]);
        g_wgt[idx] = __float2half_rn(Wg[k * 256 + t]);
    }
    // Wout^T: [n=64][k=256] halfs, rowBytes 512.
    const int n = t & 63, kb = (t >> 6) * 64;
    #pragma unroll 4
    for (int kk = 0; kk < 64; kk++) {
        const int k = kb + kk;
        g_wot[bo16(n, k, 512) >> 1] = __float2half_rn(Wo[k * 64 + n]);
    }
}

// ---------------------------------------------------------------------------
// K1: LN(msa) -> Ash (f16); v = A @ Wv (staged->g_v f16), gate = sigmoid -> u16.
// SMEM: Ash 16KB @0 ; Wsh 32KB @16384 ; Dsh [32][136] halfs @49152. Total 57856.
// ---------------------------------------------------------------------------
__global__ __launch_bounds__(256, 2) void k1_v_gate(
    const float* __restrict__ msa,
    const float* __restrict__ ln_g, const float* __restrict__ ln_b)
{
    extern __shared__ char smc[];
    char*   Ash = smc;                       // [128 rows][64 halfs] sw
    char*   Wsh = smc + 16384;               // [256 rows][64 halfs] sw
    __half* Dsh = (__half*)(smc + 49152);    // [32][136]

    const int t    = threadIdx.x;
    const int lane = t & 31;
    const int warp = t >> 5;
    const int wm   = warp >> 1;
    const int wn   = warp & 1;
    const int r    = lane >> 2;
    const int cq   = lane & 3;

    const int rb    = blockIdx.x * 128;
    const int s_idx = rb / I_DIM;
    const int j0    = rb - s_idx * I_DIM;

    const float lg0 = ln_g[lane], lg1 = ln_g[lane + 32];
    const float lb0 = ln_b[lane], lb1 = ln_b[lane + 32];
    #pragma unroll 4
    for (int rr = 0; rr < 16; rr++) {
        const int row = warp * 16 + rr;
        const float* x = msa + (size_t)(rb + row) * CM;
        float x0 = x[lane], x1 = x[lane + 32];
        float s = x0 + x1, s2 = x0 * x0 + x1 * x1;
        #pragma unroll
        for (int o = 16; o; o >>= 1) {
            s  += __shfl_xor_sync(0xffffffffu, s,  o);
            s2 += __shfl_xor_sync(0xffffffffu, s2, o);
        }
        float mu  = s * (1.f / 64.f);
        float var = s2 * (1.f / 64.f) - mu * mu;
        float rs  = rsqrtf(var + LN_EPS);
        *(__half*)(Ash + bo16(row, lane,      128)) =
            __float2half_rn((x0 - mu) * rs * lg0 + lb0);
        *(__half*)(Ash + bo16(row, lane + 32, 128)) =
            __float2half_rn((x1 - mu) * rs * lg1 + lb1);
    }

    for (int p = 0; p < 2; p++) {
        __syncthreads();
        {   // Wsh <- pre-swizzled W^T (2048 float4)
            const float4* src = (const float4*)(p ? g_wgt : g_wvt);
            float4* dst = (float4*)Wsh;
            #pragma unroll
            for (int u = 0; u < 8; u++) dst[u * 256 + t] = src[u * 256 + t];
        }
        __syncthreads();

        for (int nh = 0; nh < 2; nh++) {
            float acc[2][8][4];
            #pragma unroll
            for (int mt = 0; mt < 2; mt++)
                #pragma unroll
                for (int nt = 0; nt < 8; nt++)
                    #pragma unroll
                    for (int e = 0; e < 4; e++) acc[mt][nt][e] = 0.f;

            #pragma unroll
            for (int ks = 0; ks < 4; ks++) {              // K=64, 16 per step
                const int klo = ks * 16 + 2 * cq, khi = klo + 8;
                uint32_t a[2][4];
                #pragma unroll
                for (int mt = 0; mt < 2; mt++) {
                    const int row0 = wm * 32 + mt * 16 + r;
                    a[mt][0] = *(const uint32_t*)(Ash + bo16(row0,     klo, 128));
                    a[mt][1] = *(const uint32_t*)(Ash + bo16(row0 + 8, klo, 128));
                    a[mt][2] = *(const uint32_t*)(Ash + bo16(row0,     khi, 128));
                    a[mt][3] = *(const uint32_t*)(Ash + bo16(row0 + 8, khi, 128));
                }
                uint32_t b[8][2];
                #pragma unroll
                for (int nt = 0; nt < 8; nt++) {
                    const int n = nh * 128 + wn * 64 + nt * 8 + r;
                    b[nt][0] = *(const uint32_t*)(Wsh + bo16(n, klo, 128));
                    b[nt][1] = *(const uint32_t*)(Wsh + bo16(n, khi, 128));
                }
                #pragma unroll
                for (int mt = 0; mt < 2; mt++)
                    #pragma unroll
                    for (int nt = 0; nt < 8; nt++)
                        mma_f16(acc[mt][nt], a[mt], b[nt]);
            }

            if (p == 0) {
                #pragma unroll
                for (int cb = 0; cb < 4; cb++) {
                    if (wn == (cb >> 1)) {
                        const int ntlo = (cb & 1) * 4;
                        #pragma unroll
                        for (int mt = 0; mt < 2; mt++) {
                            #pragma unroll
                            for (int nt2 = 0; nt2 < 4; nt2++) {
                                const int nt  = ntlo + nt2;
                                const int ncl = nt2 * 8 + 2 * cq;
                                const int row = wm * 32 + mt * 16 + r;
                                Dsh[ncl * 136 + row]           = __float2half_rn(acc[mt][nt][0]);
                                Dsh[(ncl + 1) * 136 + row]     = __float2half_rn(acc[mt][nt][1]);
                                Dsh[ncl * 136 + row + 8]       = __float2half_rn(acc[mt][nt][2]);
                                Dsh[(ncl + 1) * 136 + row + 8] = __float2half_rn(acc[mt][nt][3]);
                            }
                        }
                    }
                    __syncthreads();
                    // 32 nc rows x 128 halfs (256B) coalesced -> g_v
                    #pragma unroll
                    for (int u = 0; u < 2; u++) {
                        const int idx  = u * 256 + t;     // 0..511
                        const int q    = idx & 15;        // float4 within row
                        const int rloc = idx >> 4;        // 0..31
                        const int nc   = nh * 128 + cb * 32 + rloc;
                        const int h    = nc >> 5, c = nc & 31;
                        float4 val = *(const float4*)(Dsh + rloc * 136 + q * 8);
                        __half* drow =
                            g_v + ((size_t)h * 16384 + s_idx * 32 + c) * I_DIM + j0;
                        ((float4*)drow)[q] = val;
                    }
                    __syncthreads();
                }
            } else {
                #pragma unroll
                for (int mt = 0; mt < 2; mt++) {
                    #pragma unroll
                    for (int nt = 0; nt < 8; nt++) {
                        const int nc  = nh * 128 + wn * 64 + nt * 8 + 2 * cq;
                        const int row = wm * 32 + mt * 16 + r;
                        const size_t base = (size_t)(rb + row) * HC + nc;
                        const float s0 = 1.f / (1.f + __expf(-acc[mt][nt][0]));
                        const float s1 = 1.f / (1.f + __expf(-acc[mt][nt][1]));
                        const float s2 = 1.f / (1.f + __expf(-acc[mt][nt][2]));
                        const float s3 = 1.f / (1.f + __expf(-acc[mt][nt][3]));
                        *(uint32_t*)(g_gate16 + base)                  = pack_gate(s0, s1);
                        *(uint32_t*)(g_gate16 + base + (size_t)8 * HC) = pack_gate(s2, s3);
                    }
                }
            }
        }
    }
}

// ---------------------------------------------------------------------------
// K2: bias[i][h][j] = LN(pair[i][j]) @ W_bias.  Warp-per-row, 8 rows/block.
// ---------------------------------------------------------------------------
__global__ __launch_bounds__(256) void k2_bias(
    const float* __restrict__ pair,
    const float* __restrict__ gz, const float* __restrict__ bz,
    const float* __restrict__ Wb)
{
    __shared__ float Wbs[8 * 128];
    __shared__ float gzs[128], bzs[128];

    const int t = threadIdx.x;
    const int lane = t & 31, warp = t >> 5;
    const int row = blockIdx.x * 8 + warp;
    const int i = row / I_DIM, j = row - i * I_DIM;

    #pragma unroll
    for (int u = 0; u < 4; u++) {
        const int idx = u * 256 + t;
        const int h = idx >> 7, col = idx & 127;
        Wbs[h * 128 + col] = Wb[col * 8 + h];
    }
    if (t < 128) { gzs[t] = gz[t]; bzs[t] = bz[t]; }
    __syncthreads();

    const float* x = pair + (size_t)row * CZ;
    float xv[4];
    #pragma unroll
    for (int c = 0; c < 4; c++) xv[c] = x[lane + 32 * c];

    float s = 0.f, s2 = 0.f;
    #pragma unroll
    for (int c = 0; c < 4; c++) { s += xv[c]; s2 += xv[c] * xv[c]; }
    #pragma unroll
    for (int o = 16; o; o >>= 1) {
        s  += __shfl_xor_sync(0xffffffffu, s,  o);
        s2 += __shfl_xor_sync(0xffffffffu, s2, o);
    }
    const float mu  = s * (1.f / 128.f);
    const float var = s2 * (1.f / 128.f) - mu * mu;
    const float rs  = rsqrtf(var + LN_EPS);

    float p[8];
    #pragma unroll
    for (int h = 0; h < 8; h++) p[h] = 0.f;
    #pragma unroll
    for (int c = 0; c < 4; c++) {
        const int col = lane + 32 * c;
        const float xn = (xv[c] - mu) * rs * gzs[col] + bzs[col];
        #pragma unroll
        for (int h = 0; h < 8; h++) p[h] += xn * Wbs[h * 128 + col];
    }
    #pragma unroll
    for (int h = 0; h < 8; h++) {
        #pragma unroll
        for (int o = 16; o; o >>= 1) p[h] += __shfl_xor_sync(0xffffffffu, p[h], o);
    }
    if (lane < 8)
        g_bias[((size_t)i * H_DIM + lane) * I_DIM + j] = p[lane];
}

// ---------------------------------------------------------------------------
// K3: w[h][i][j] = softmax_j(bias[i][h][j])  -> f16 stores
// ---------------------------------------------------------------------------
__global__ __launch_bounds__(128) void k3_softmax()
{
    __shared__ float red[4];
    __shared__ float bval;

    const int t = threadIdx.x;
    const int lane = t & 31, warp = t >> 5;
    const int b = blockIdx.x;
    const int i = b >> 3, h = b & 7;

    const float* src = g_bias + ((size_t)i * H_DIM + h) * I_DIM;
    float x0 = src[t], x1 = src[t + 128], x2 = src[t + 256];

    float m = fmaxf(x0, fmaxf(x1, x2));
    #pragma unroll
    for (int o = 16; o; o >>= 1) m = fmaxf(m, __shfl_xor_sync(0xffffffffu, m, o));
    if (lane == 0) red[warp] = m;
    __syncthreads();
    if (t == 0) bval = fmaxf(fmaxf(red[0], red[1]), fmaxf(red[2], red[3]));
    __syncthreads();
    const float mx = bval;

    float e0 = __expf(x0 - mx), e1 = __expf(x1 - mx), e2 = __expf(x2 - mx);
    float s = e0 + e1 + e2;
    #pragma unroll
    for (int o = 16; o; o >>= 1) s += __shfl_xor_sync(0xffffffffu, s, o);
    __syncthreads();
    if (lane == 0) red[warp] = s;
    __syncthreads();
    if (t == 0) bval = red[0] + red[1] + red[2] + red[3];
    __syncthreads();
    const float inv = 1.f / bval;

    __half* dst = g_w + ((size_t)h * I_DIM + i) * I_DIM;
    dst[t]       = __float2half_rn(e0 * inv);
    dst[t + 128] = __float2half_rn(e1 * inv);
    dst[t + 256] = __float2half_rn(e2 * inv);
}

// ---------------------------------------------------------------------------
// K4: fp16 mma GEMM per head. Grid (3, 128, 8); 2 CTAs/SM; 3-stage, 1 barrier.
// K=384 in 6 chunks of 64 halfs (128B rows). SMEM 3 x 32KB = 96KB.
// ---------------------------------------------------------------------------
__global__ __launch_bounds__(256, 2) void k4_gemm()
{
    extern __shared__ char smc[];
    const uint32_t sb = smem_u32(smc);

    const int t    = threadIdx.x;
    const int lane = t & 31;
    const int warp = t >> 5;
    const int wm   = warp >> 1;
    const int wn   = warp & 1;
    const int r    = lane >> 2;
    const int cq   = lane & 3;

    const int i0 = blockIdx.x * 128;
    const int n0 = blockIdx.y * 128;
    const int h  = blockIdx.z;

    const __half* Ag = g_w + ((size_t)h * I_DIM + i0) * I_DIM;
    const __half* Bg = g_v + ((size_t)h * 16384 + n0) * I_DIM;

    float acc[2][8][4];
    #pragma unroll
    for (int mt = 0; mt < 2; mt++)
        #pragma unroll
        for (int nt = 0; nt < 8; nt++)
            #pragma unroll
            for (int e = 0; e < 4; e++) acc[mt][nt][e] = 0.f;

    auto LOAD = [&](int kc, int buf) {
        const uint32_t Ab = sb + buf * 32768;
        const uint32_t Bb = Ab + 16384;
        const int k0 = kc * 64;
        #pragma unroll
        for (int u = 0; u < 4; u++) {
            int lin = u * 256 + t;
            int row = lin >> 3, q = lin & 7;
            cp_async16(Ab + swz128(row * 128 + q * 16),
                       Ag + (size_t)row * I_DIM + k0 + q * 8);
        }
        #pragma unroll
        for (int u = 0; u < 4; u++) {
            int lin = u * 256 + t;
            int row = lin >> 3, q = lin & 7;
            cp_async16(Bb + swz128(row * 128 + q * 16),
                       Bg + (size_t)row * I_DIM + k0 + q * 8);
        }
        cp_commit();
    };

    LOAD(0, 0);
    LOAD(1, 1);

    #pragma unroll 1
    for (int kc = 0; kc < 6; kc++) {
        const int buf = kc % 3;
        if (kc < 5) cp_wait1(); else cp_wait0();
        __syncthreads();
        if (kc + 2 < 6) LOAD(kc + 2, (kc + 2) % 3);

        const char* Ab = smc + buf * 32768;
        const char* Bb = Ab + 16384;

        #pragma unroll
        for (int ks = 0; ks < 4; ks++) {              // 64 halfs, 16 per step
            const int klo = ks * 16 + 2 * cq, khi = klo + 8;
            uint32_t a[2][4];
            #pragma unroll
            for (int mt = 0; mt < 2; mt++) {
                const int row0 = wm * 32 + mt * 16 + r;
                a[mt][0] = *(const uint32_t*)(Ab + bo16(row0,     klo, 128));
                a[mt][1] = *(const uint32_t*)(Ab + bo16(row0 + 8, klo, 128));
                a[mt][2] = *(const uint32_t*)(Ab + bo16(row0,     khi, 128));
                a[mt][3] = *(const uint32_t*)(Ab + bo16(row0 + 8, khi, 128));
            }
            uint32_t b[8][2];
            #pragma unroll
            for (int nt = 0; nt < 8; nt++) {
                const int rown = wn * 64 + nt * 8 + r;
                b[nt][0] = *(const uint32_t*)(Bb + bo16(rown, klo, 128));
                b[nt][1] = *(const uint32_t*)(Bb + bo16(rown, khi, 128));
            }
            #pragma unroll
            for (int mt = 0; mt < 2; mt++)
                #pragma unroll
                for (int nt = 0; nt < 8; nt++)
                    mma_f16(acc[mt][nt], a[mt], b[nt]);
        }
    }

    #pragma unroll
    for (int mt = 0; mt < 2; mt++) {
        #pragma unroll
        for (int nt = 0; nt < 8; nt++) {
            const int n_lo = n0 + wn * 64 + nt * 8 + 2 * cq;
            const int s = n_lo >> 5, c = n_lo & 31;
            const int i = i0 + wm * 32 + mt * 16 + r;
            const size_t base0 = ((size_t)s * I_DIM + i) * HC + h * 32 + c;
            const size_t base1 = base0 + (size_t)8 * HC;
            const uint32_t u0 = *(const uint32_t*)(g_gate16 + base0);
            const uint32_t u1 = *(const uint32_t*)(g_gate16 + base1);
            __half2 w0, w1;
            w0.x = __float2half_rn((float)(u0 & 0xffffu) * GATE_INV * acc[mt][nt][0]);
            w0.y = __float2half_rn((float)(u0 >> 16)     * GATE_INV * acc[mt][nt][1]);
            w1.x = __float2half_rn((float)(u1 & 0xffffu) * GATE_INV * acc[mt][nt][2]);
            w1.y = __float2half_rn((float)(u1 >> 16)     * GATE_INV * acc[mt][nt][3]);
            *(__half2*)(g_wt + base0) = w0;
            *(__half2*)(g_wt + base1) = w1;
        }
    }
}

// ---------------------------------------------------------------------------
// K5: out = g_wt @ W_out via fp16 mma. 2 CTAs/SM; 3-stage, 1 barrier.
// K=256 in 4 chunks of 64 halfs. SMEM: Wsh 32KB @0 ; 3 x 16KB @32768. Total 80KB.
// ---------------------------------------------------------------------------
__global__ __launch_bounds__(256, 2) void k5_out(float* __restrict__ outp)
{
    extern __shared__ char smc[];
    const uint32_t sb = smem_u32(smc);
    char* Wsh = smc;

    const int t    = threadIdx.x;
    const int lane = t & 31;
    const int warp = t >> 5;
    const int wm   = warp >> 1;
    const int wn   = warp & 1;
    const int r    = lane >> 2;
    const int cq   = lane & 3;
    const int rb   = blockIdx.x * 128;

    {   // Wout^T pre-swizzled halfs (2048 float4)
        const float4* src = (const float4*)g_wot;
        float4* dst = (float4*)Wsh;
        #pragma unroll
        for (int u = 0; u < 8; u++) dst[u * 256 + t] = src[u * 256 + t];
    }

    const __half* Agl = g_wt + (size_t)rb * HC;

    auto LOAD = [&](int kc, int buf) {
        const uint32_t Ab = sb + 32768 + buf * 16384;
        const int k0 = kc * 64;
        #pragma unroll
        for (int u = 0; u < 4; u++) {
            int lin = u * 256 + t;
            int row = lin >> 3, q = lin & 7;
            cp_async16(Ab + swz128(row * 128 + q * 16),
                       Agl + (size_t)row * HC + k0 + q * 8);
        }
        cp_commit();
    };

    float acc[2][4][4];
    #pragma unroll
    for (int mt = 0; mt < 2; mt++)
        #pragma unroll
        for (int nt = 0; nt < 4; nt++)
            #pragma unroll
            for (int e = 0; e < 4; e++) acc[mt][nt][e] = 0.f;

    LOAD(0, 0);
    LOAD(1, 1);

    #pragma unroll 1
    for (int kc = 0; kc < 4; kc++) {
        const int buf = kc % 3;
        if (kc < 3) cp_wait1(); else cp_wait0();
        __syncthreads();
        if (kc + 2 < 4) LOAD(kc + 2, (kc + 2) % 3);

        const char* Ab = smc + 32768 + buf * 16384;

        #pragma unroll
        for (int ks = 0; ks < 4; ks++) {
            const int klo = ks * 16 + 2 * cq, khi = klo + 8;
            const int gklo = kc * 64 + klo, gkhi = kc * 64 + khi;
            uint32_t a[2][4];
            #pragma unroll
            for (int mt = 0; mt < 2; mt++) {
                const int row0 = wm * 32 + mt * 16 + r;
                a[mt][0] = *(const uint32_t*)(Ab + bo16(row0,     klo, 128));
                a[mt][1] = *(const uint32_t*)(Ab + bo16(row0 + 8, klo, 128));
                a[mt][2] = *(const uint32_t*)(Ab + bo16(row0,     khi, 128));
                a[mt][3] = *(const uint32_t*)(Ab + bo16(row0 + 8, khi, 128));
            }
            uint32_t b[4][2];
            #pragma unroll
            for (int nt = 0; nt < 4; nt++) {
                const int n = wn * 32 + nt * 8 + r;
                b[nt][0] = *(const uint32_t*)(Wsh + bo16(n, gklo, 512));
                b[nt][1] = *(const uint32_t*)(Wsh + bo16(n, gkhi, 512));
            }
            #pragma unroll
            for (int mt = 0; mt < 2; mt++)
                #pragma unroll
                for (int nt = 0; nt < 4; nt++)
                    mma_f16(acc[mt][nt], a[mt], b[nt]);
        }
    }

    #pragma unroll
    for (int mt = 0; mt < 2; mt++) {
        #pragma unroll
        for (int nt = 0; nt < 4; nt++) {
            const int n   = wn * 32 + nt * 8 + 2 * cq;
            const int row = rb + wm * 32 + mt * 16 + r;
            *(float2*)(outp + (size_t)row * CM + n) =
                make_float2(acc[mt][nt][0], acc[mt][nt][1]);
            *(float2*)(outp + (size_t)(row + 8) * CM + n) =
                make_float2(acc[mt][nt][2], acc[mt][nt][3]);
        }
    }
}

// ---------------------------------------------------------------------------
extern "C" void kernel_launch(void* const* d_in, const int* in_sizes, int n_in,
                              void* d_out, int out_size)
{
    (void)in_sizes; (void)n_in; (void)out_size;
    const float* msa  = (const float*)d_in[0];
    const float* pair = (const float*)d_in[1];
    const float* lmg  = (const float*)d_in[2];
    const float* lmb  = (const float*)d_in[3];
    const float* lpg  = (const float*)d_in[4];
    const float* lpb  = (const float*)d_in[5];
    const float* Wv   = (const float*)d_in[6];
    const float* Wb   = (const float*)d_in[7];
    const float* Wg   = (const float*)d_in[8];
    const float* Wo   = (const float*)d_in[9];
    float* outp = (float*)d_out;

    cudaFuncSetAttribute(k1_v_gate, cudaFuncAttributeMaxDynamicSharedMemorySize, 57856);
    cudaFuncSetAttribute(k4_gemm,   cudaFuncAttributeMaxDynamicSharedMemorySize, 98304);
    cudaFuncSetAttribute(k5_out,    cudaFuncAttributeMaxDynamicSharedMemorySize, 81920);

    k0_prep<<<1, 256>>>(Wv, Wg, Wo);
    k1_v_gate<<<(S_DIM * I_DIM) / 128, 256, 57856>>>(msa, lmg, lmb);
    k2_bias<<<(I_DIM * I_DIM) / 8, 256>>>(pair, lpg, lpb, Wb);
    k3_softmax<<<I_DIM * H_DIM, 128>>>();
    k4_gemm<<<dim3(3, 128, 8), 256, 98304>>>();
    k5_out<<<(S_DIM * I_DIM) / 128, 256, 81920>>>(outp);
}